// round 7
// baseline (speedup 1.0000x reference)
#include <cuda_runtime.h>
#include <math.h>

// Problem constants
#define BB   2
#define SS   2048
#define DD   1024
#define HH   16
#define HDIM 64
#define TOK  (BB*SS)           // 4096 rows
#define NSCALE 0.125f          // 1/sqrt(64)
#define LOG2E  1.4426950408889634f

// ---------------------------------------------------------------------------
// Scratch (static __device__ arrays; no allocation allowed)
// ---------------------------------------------------------------------------
__device__ float g_xq[TOK*DD];
__device__ float g_xk[TOK*DD];
__device__ float g_xv[TOK*DD];
__device__ float g_Q [TOK*DD];   // head layout [B,H,S,HD]
__device__ float g_K [TOK*DD];
__device__ float g_Kt[TOK*DD];   // transposed [B,H,HD,S]
__device__ float g_Vt[TOK*DD];
__device__ float g_O [TOK*DD];
__device__ float g_Wq[DD*DD];    // tf32-rounded, TRANSPOSED [n][k]
__device__ float g_Wk[DD*DD];
__device__ float g_Wv[DD*DD];
__device__ float g_Wo[DD*DD];

// ---------------------------------------------------------------------------
// helpers
// ---------------------------------------------------------------------------
__device__ __forceinline__ float tf32r(float x) {
    unsigned u;
    asm("cvt.rna.tf32.f32 %0, %1;" : "=r"(u) : "f"(x));
    return __uint_as_float(u);
}

__device__ __forceinline__ float ex2(float x) {
    float y;
    asm("ex2.approx.ftz.f32 %0, %1;" : "=f"(y) : "f"(x));
    return y;
}

__device__ __forceinline__ void mma8(float* d, const unsigned* a, unsigned b0, unsigned b1) {
    asm volatile(
        "mma.sync.aligned.m16n8k8.row.col.f32.tf32.tf32.f32 "
        "{%0,%1,%2,%3}, {%4,%5,%6,%7}, {%8,%9}, {%0,%1,%2,%3};"
        : "+f"(d[0]), "+f"(d[1]), "+f"(d[2]), "+f"(d[3])
        : "r"(a[0]), "r"(a[1]), "r"(a[2]), "r"(a[3]), "r"(b0), "r"(b1));
}

__device__ __forceinline__ void ldsm4(unsigned& r0, unsigned& r1, unsigned& r2, unsigned& r3,
                                      unsigned addr) {
    asm volatile("ldmatrix.sync.aligned.m8n8.x4.shared.b16 {%0,%1,%2,%3}, [%4];"
        : "=r"(r0), "=r"(r1), "=r"(r2), "=r"(r3) : "r"(addr));
}

__device__ __forceinline__ void cpa16(unsigned dst, const void* src) {
    asm volatile("cp.async.cg.shared.global [%0], [%1], 16;" :: "r"(dst), "l"(src));
}
__device__ __forceinline__ void cpa_commit() { asm volatile("cp.async.commit_group;"); }
__device__ __forceinline__ void cpa_wait0()  { asm volatile("cp.async.wait_group 0;"); }
__device__ __forceinline__ void cpa_wait1()  { asm volatile("cp.async.wait_group 1;"); }

// ---------------------------------------------------------------------------
// Weight pre-round + transpose: dst[n][k] = tf32(src[k][n])
// grid (DD/32, DD/32, 4), block (32, 8)
// ---------------------------------------------------------------------------
__global__ __launch_bounds__(256) void roundw_t(
    const float* __restrict__ w0, const float* __restrict__ w1,
    const float* __restrict__ w2, const float* __restrict__ w3,
    float* __restrict__ d0, float* __restrict__ d1,
    float* __restrict__ d2, float* __restrict__ d3)
{
    __shared__ float tile[32][33];
    const float* src; float* dst;
    switch (blockIdx.z) {
        case 0: src = w0; dst = d0; break;
        case 1: src = w1; dst = d1; break;
        case 2: src = w2; dst = d2; break;
        default: src = w3; dst = d3; break;
    }
    int k0 = blockIdx.x * 32, n0 = blockIdx.y * 32;
    int x = threadIdx.x;
    #pragma unroll
    for (int r = threadIdx.y; r < 32; r += 8)
        tile[r][x] = src[(size_t)(k0 + r) * DD + n0 + x];
    __syncthreads();
    #pragma unroll
    for (int r = threadIdx.y; r < 32; r += 8)
        dst[(size_t)(n0 + r) * DD + k0 + x] = tf32r(tile[x][r]);
}

// ---------------------------------------------------------------------------
// Block reduction (256 threads)
// ---------------------------------------------------------------------------
__device__ __forceinline__ float blk_sum256(float v) {
    __shared__ float red[8];
    int lane = threadIdx.x & 31;
    int w    = threadIdx.x >> 5;
    #pragma unroll
    for (int o = 16; o > 0; o >>= 1) v += __shfl_xor_sync(0xffffffffu, v, o);
    __syncthreads();
    if (lane == 0) red[w] = v;
    __syncthreads();
    return red[0]+red[1]+red[2]+red[3]+red[4]+red[5]+red[6]+red[7];
}

// ---------------------------------------------------------------------------
// Fused triple LayerNorm (outputs tf32-rounded)
// ---------------------------------------------------------------------------
__global__ __launch_bounds__(256) void ln3_kernel(
    const float* __restrict__ data,
    const float* __restrict__ gk, const float* __restrict__ bk,
    const float* __restrict__ gq, const float* __restrict__ bq,
    const float* __restrict__ gv, const float* __restrict__ bv,
    float* __restrict__ xq, float* __restrict__ xk, float* __restrict__ xv)
{
    int row = blockIdx.x;
    int t   = threadIdx.x;
    const float4 x4 = ((const float4*)(data + (size_t)row * DD))[t];
    float s = x4.x + x4.y + x4.z + x4.w;
    float mean = blk_sum256(s) * (1.0f / DD);
    float d0 = x4.x - mean, d1 = x4.y - mean, d2 = x4.z - mean, d3 = x4.w - mean;
    float sq = d0*d0 + d1*d1 + d2*d2 + d3*d3;
    float var = blk_sum256(sq) * (1.0f / DD);
    float r = rsqrtf(var + 1e-5f);
    float n0 = d0*r, n1 = d1*r, n2 = d2*r, n3 = d3*r;

    float4 g4, b4, o4;
    size_t base = (size_t)row * DD;

    g4 = ((const float4*)gq)[t]; b4 = ((const float4*)bq)[t];
    o4 = make_float4(tf32r(n0*g4.x + b4.x), tf32r(n1*g4.y + b4.y),
                     tf32r(n2*g4.z + b4.z), tf32r(n3*g4.w + b4.w));
    ((float4*)(xq + base))[t] = o4;

    g4 = ((const float4*)gk)[t]; b4 = ((const float4*)bk)[t];
    o4 = make_float4(tf32r(n0*g4.x + b4.x), tf32r(n1*g4.y + b4.y),
                     tf32r(n2*g4.z + b4.z), tf32r(n3*g4.w + b4.w));
    ((float4*)(xk + base))[t] = o4;

    g4 = ((const float4*)gv)[t]; b4 = ((const float4*)bv)[t];
    o4 = make_float4(tf32r(n0*g4.x + b4.x), tf32r(n1*g4.y + b4.y),
                     tf32r(n2*g4.z + b4.z), tf32r(n3*g4.w + b4.w));
    ((float4*)(xv + base))[t] = o4;
}

// ---------------------------------------------------------------------------
// tf32 GEMM body, cp.async double-buffered, BK=32, ALL fragments via ldmatrix.
// A [M,K] (or head-layout gather), W TRANSPOSED [N,K].
// MODE_OUT: 0 row-major | 1 head layout | 2 head layout + transposed | 3 transposed only
// ---------------------------------------------------------------------------
template<int MODE_IN, int MODE_OUT, int ROUND>
__device__ __forceinline__ void gemm_body(
    const float* __restrict__ A, const float* __restrict__ Wt,
    const float* __restrict__ bias, float* __restrict__ C, float* __restrict__ Ct)
{
    constexpr int BM = 128, BN = 128, BK = 32;
    constexpr int PITCH = 36;
    constexpr int TSZ = BM * PITCH;   // 4608 floats per tile stage
    __shared__ float As[2 * TSZ];
    __shared__ float Bs[2 * TSZ];

    int tid  = threadIdx.x;
    int lane = tid & 31;
    int w    = tid >> 5;
    int g    = lane >> 2;
    int t    = lane & 3;
    int wm   = (w >> 2) * 64;
    int wn   = (w & 3) * 32;
    int bm   = blockIdx.y * BM;
    int bn   = blockIdx.x * BN;

    int lr = tid >> 1;            // 0..127
    int lc = (tid & 1) * 16;      // 0 or 16

    unsigned as_base = (unsigned)__cvta_generic_to_shared(As);
    unsigned bs_base = (unsigned)__cvta_generic_to_shared(Bs);

    // ldmatrix per-lane addresses (floats): A rows m, B rows n; cols k
    unsigned a_ld = as_base + (((lane & 15) * PITCH + (lane >> 4) * 4) * 4);
    unsigned b_ld = bs_base + (((lane & 7)  * PITCH + (lane >> 3) * 4) * 4);

    float acc[4][4][4];
    #pragma unroll
    for (int i = 0; i < 4; i++)
        #pragma unroll
        for (int j = 0; j < 4; j++)
            #pragma unroll
            for (int q = 0; q < 4; q++) acc[i][j][q] = 0.f;

    auto load_tile = [&](int it, int stg) {
        int kk = it * BK;
        int gm = bm + lr;
        int gk = kk + lc;
        const float* pa;
        if (MODE_IN == 0) {
            pa = &A[(size_t)gm * DD + gk];
        } else {
            int b  = gm >> 11, s2 = gm & (SS - 1);
            int h  = gk >> 6,  hd = gk & (HDIM - 1);
            pa = &A[(((size_t)(b*HH + h) * SS + s2) * HDIM) + hd];
        }
        unsigned da = as_base + (stg * TSZ + lr * PITCH + lc) * 4;
        #pragma unroll
        for (int i = 0; i < 4; i++) cpa16(da + i*16, pa + i*4);
        const float* pb = &Wt[(size_t)(bn + lr) * DD + kk + lc];
        unsigned db = bs_base + (stg * TSZ + lr * PITCH + lc) * 4;
        #pragma unroll
        for (int i = 0; i < 4; i++) cpa16(db + i*16, pb + i*4);
    };

    constexpr int KITER = DD / BK;   // 32
    load_tile(0, 0);
    cpa_commit();

    for (int it = 0; it < KITER; it++) {
        int cur = it & 1;
        if (it + 1 < KITER) {
            load_tile(it + 1, cur ^ 1);
            cpa_commit();
            cpa_wait1();
        } else {
            cpa_wait0();
        }
        __syncthreads();

        unsigned ab = a_ld + cur * TSZ * 4;
        unsigned bb = b_ld + cur * TSZ * 4;

        #pragma unroll
        for (int kh = 0; kh < 2; kh++) {          // k halves of 16
            // B fragments: ldsm.x4 per ni covers 2 ks (8 n rows x 16 k floats)
            unsigned bf[4][4];
            #pragma unroll
            for (int ni = 0; ni < 4; ni++)
                ldsm4(bf[ni][0], bf[ni][1], bf[ni][2], bf[ni][3],
                      bb + ((wn + ni*8) * PITCH + kh*16) * 4);
            #pragma unroll
            for (int kp = 0; kp < 2; kp++) {      // ks within half
                int k0 = kh*16 + kp*8;
                unsigned af[4][4];
                #pragma unroll
                for (int mi = 0; mi < 4; mi++)
                    ldsm4(af[mi][0], af[mi][1], af[mi][2], af[mi][3],
                          ab + ((wm + mi*16) * PITCH + k0) * 4);
                #pragma unroll
                for (int mi = 0; mi < 4; mi++)
                    #pragma unroll
                    for (int ni = 0; ni < 4; ni++)
                        mma8(acc[mi][ni], af[mi], bf[ni][2*kp], bf[ni][2*kp + 1]);
            }
        }
        __syncthreads();
    }

    // ---- epilogue ----
    #pragma unroll
    for (int mi = 0; mi < 4; mi++) {
        #pragma unroll
        for (int ni = 0; ni < 4; ni++) {
            int row = bm + wm + mi * 16 + g;
            int col = bn + wn + ni * 8 + 2 * t;
            float2 bia = *(const float2*)&bias[col];
            float2 v0, v1;
            if (ROUND) {
                v0 = make_float2(tf32r(acc[mi][ni][0] + bia.x), tf32r(acc[mi][ni][1] + bia.y));
                v1 = make_float2(tf32r(acc[mi][ni][2] + bia.x), tf32r(acc[mi][ni][3] + bia.y));
            } else {
                v0 = make_float2(acc[mi][ni][0] + bia.x, acc[mi][ni][1] + bia.y);
                v1 = make_float2(acc[mi][ni][2] + bia.x, acc[mi][ni][3] + bia.y);
            }
            int h = col >> 6, hd = col & (HDIM - 1);
            int b0i = row >> 11,       s0 = row & (SS - 1);
            int b1i = (row + 8) >> 11, s1 = (row + 8) & (SS - 1);
            if (MODE_OUT == 0) {
                *(float2*)&C[(size_t)row * DD + col]       = v0;
                *(float2*)&C[(size_t)(row + 8) * DD + col] = v1;
            }
            if (MODE_OUT == 1 || MODE_OUT == 2) {
                *(float2*)&C[((size_t)(b0i*HH + h) * SS + s0) * HDIM + hd] = v0;
                *(float2*)&C[((size_t)(b1i*HH + h) * SS + s1) * HDIM + hd] = v1;
            }
            if (MODE_OUT == 2 || MODE_OUT == 3) {
                float* T0 = Ct + ((size_t)(b0i*HH + h) * HDIM + hd) * SS;
                float* T1 = Ct + ((size_t)(b1i*HH + h) * HDIM + hd) * SS;
                T0[s0]      = v0.x;
                T0[SS + s0] = v0.y;   // hd+1 row
                T1[s1]      = v1.x;
                T1[SS + s1] = v1.y;
            }
        }
    }
}

// Batched Q/K/V projection: grid (8, 32, 3)
__global__ __launch_bounds__(256, 2) void gemm_qkv(
    const float* __restrict__ xq, const float* __restrict__ xk, const float* __restrict__ xv,
    const float* __restrict__ Wq, const float* __restrict__ Wk, const float* __restrict__ Wv,
    const float* __restrict__ bq, const float* __restrict__ bk, const float* __restrict__ bv,
    float* __restrict__ Q, float* __restrict__ K,
    float* __restrict__ Kt, float* __restrict__ Vt)
{
    if (blockIdx.z == 0)      gemm_body<0, 1, 1>(xq, Wq, bq, Q, nullptr);
    else if (blockIdx.z == 1) gemm_body<0, 2, 1>(xk, Wk, bk, K, Kt);
    else                      gemm_body<0, 3, 1>(xv, Wv, bv, nullptr, Vt);
}

// Output projection: grid (8, 32)
__global__ __launch_bounds__(256, 2) void gemm_out(
    const float* __restrict__ A, const float* __restrict__ Wt,
    const float* __restrict__ bias, float* __restrict__ C)
{
    gemm_body<1, 0, 0>(A, Wt, bias, C, nullptr);
}

// ---------------------------------------------------------------------------
// FUSED double-pass flash attention (Hopfield update + retrieval).
//   pass 1: Q2 = softmax(b Q K^T) K      (V^T tile source = Kt)
//   pass 2: O  = softmax(b Q2 K^T) V     (V^T tile source = Vt)
// 256 threads = 8 warps; CTA = 128 queries (16/warp); K-tile 64 keys.
// ---------------------------------------------------------------------------
#define TSP 68
#define PSP 68
#define TILESZ (64*TSP)
#define ATTN_SMEM ((4*TILESZ + 8*16*PSP) * 4)

__global__ __launch_bounds__(256, 2) void attn_fused(
    const float* __restrict__ Qin, const float* __restrict__ Kin,
    const float* __restrict__ Ktin, const float* __restrict__ Vtin,
    float* __restrict__ Out)
{
    extern __shared__ float sm[];
    float* Ks = sm;                 // [2][64][TSP]  keys x hd
    float* Ts = sm + 2 * TILESZ;    // [2][64][TSP]  hd x keys (V^T tile)
    float* Ps = sm + 4 * TILESZ;    // [8][16][PSP]
    unsigned ks_base = (unsigned)__cvta_generic_to_shared(Ks);
    unsigned ts_base = (unsigned)__cvta_generic_to_shared(Ts);
    unsigned ps_base = (unsigned)__cvta_generic_to_shared(Ps);

    int tid  = threadIdx.x;
    int lane = tid & 31;
    int w    = tid >> 5;
    int g    = lane >> 2;
    int t    = lane & 3;
    int bh   = blockIdx.y;
    int q0   = blockIdx.x * 128;
    size_t base = (size_t)bh * SS * HDIM;

    const float QS = NSCALE * LOG2E;

    int lrow = tid >> 2;          // 0..63
    int lcol = (tid & 3) * 16;    // 0,16,32,48

    unsigned kfrag = ks_base + (((lane & 7) * TSP + (lane >> 3) * 4) * 4);
    unsigned tfrag = ts_base + (((lane & 7) * TSP + (lane >> 3) * 4) * 4);
    float*   Pwp   = Ps + w * 16 * PSP;
    unsigned pfrag = ps_base + ((w * 16 * PSP +
                     (((lane >> 3) & 1) * 8 + (lane & 7)) * PSP + (lane >> 4) * 4) * 4);

    unsigned qa[8][4];
    {
        const float* Qp = Qin + base;
        int r0 = q0 + w * 16 + g;
        #pragma unroll
        for (int ks = 0; ks < 8; ks++) {
            qa[ks][0] = __float_as_uint(tf32r(Qp[(size_t)r0     * HDIM + ks*8 + t    ] * QS));
            qa[ks][1] = __float_as_uint(tf32r(Qp[(size_t)(r0+8) * HDIM + ks*8 + t    ] * QS));
            qa[ks][2] = __float_as_uint(tf32r(Qp[(size_t)r0     * HDIM + ks*8 + t + 4] * QS));
            qa[ks][3] = __float_as_uint(tf32r(Qp[(size_t)(r0+8) * HDIM + ks*8 + t + 4] * QS));
        }
    }

    float o[8][4];
    float l0, l1;
    constexpr int NT = SS / 64;   // 32

    auto flash_pass = [&](const float* __restrict__ Tsrc) {
        #pragma unroll
        for (int j = 0; j < 8; j++)
            #pragma unroll
            for (int q = 0; q < 4; q++) o[j][q] = 0.f;
        l0 = 0.f; l1 = 0.f;

        auto load_kv = [&](int kt, int stg) {
            const float* Kp = Kin  + base + (size_t)(kt*64 + lrow) * HDIM + lcol;
            const float* Tp = Tsrc + base + (size_t)lrow * SS + kt*64 + lcol;
            unsigned kd = ks_base + (stg * TILESZ + lrow * TSP + lcol) * 4;
            unsigned td = ts_base + (stg * TILESZ + lrow * TSP + lcol) * 4;
            #pragma unroll
            for (int i = 0; i < 4; i++) cpa16(kd + i*16, Kp + i*4);
            #pragma unroll
            for (int i = 0; i < 4; i++) cpa16(td + i*16, Tp + i*4);
        };

        load_kv(0, 0);
        cpa_commit();

        for (int kt = 0; kt < NT; kt++) {
            int cur = kt & 1;
            if (kt + 1 < NT) {
                load_kv(kt + 1, cur ^ 1);
                cpa_commit();
                cpa_wait1();
            } else {
                cpa_wait0();
            }
            __syncthreads();

            unsigned kf = kfrag + cur * TILESZ * 4;
            unsigned tf = tfrag + cur * TILESZ * 4;

            // S = Q K^T, p = 2^S, store P
            #pragma unroll
            for (int n = 0; n < 8; n++) {
                float sa[4] = {0.f, 0.f, 0.f, 0.f};
                #pragma unroll
                for (int cp = 0; cp < 4; cp++) {
                    unsigned b0, b1, b2, b3;
                    ldsm4(b0, b1, b2, b3, kf + (n*8*TSP + cp*16) * 4);
                    mma8(sa, qa[2*cp    ], b0, b1);
                    mma8(sa, qa[2*cp + 1], b2, b3);
                }
                float p0 = ex2(sa[0]), p1 = ex2(sa[1]);
                float p2 = ex2(sa[2]), p3 = ex2(sa[3]);
                l0 += p0 + p1;
                l1 += p2 + p3;
                *(float2*)(Pwp +  g      * PSP + n*8 + 2*t) = make_float2(tf32r(p0), tf32r(p1));
                *(float2*)(Pwp + (g + 8) * PSP + n*8 + 2*t) = make_float2(tf32r(p2), tf32r(p3));
            }
            __syncwarp();

            // O += P V
            unsigned pa[8][4];
            #pragma unroll
            for (int ks = 0; ks < 8; ks++)
                ldsm4(pa[ks][0], pa[ks][1], pa[ks][2], pa[ks][3], pfrag + ks*32);

            #pragma unroll
            for (int j = 0; j < 8; j++) {
                #pragma unroll
                for (int cp = 0; cp < 4; cp++) {
                    unsigned v0, v1, v2, v3;
                    ldsm4(v0, v1, v2, v3, tf + (j*8*TSP + cp*16) * 4);
                    mma8(o[j], pa[2*cp    ], v0, v1);
                    mma8(o[j], pa[2*cp + 1], v2, v3);
                }
            }
            __syncthreads();
        }

        l0 += __shfl_xor_sync(0xffffffffu, l0, 1);
        l0 += __shfl_xor_sync(0xffffffffu, l0, 2);
        l1 += __shfl_xor_sync(0xffffffffu, l1, 1);
        l1 += __shfl_xor_sync(0xffffffffu, l1, 2);
    };

    // PASS 1: Hopfield update (V = K)
    flash_pass(Ktin);

    // Q2 = O/l rescaled by QS; round, store to P region, reload as a-frags.
    {
        float s0 = QS / l0, s1 = QS / l1;
        #pragma unroll
        for (int j = 0; j < 8; j++) {
            *(float2*)(Pwp +  g      * PSP + j*8 + 2*t) =
                make_float2(tf32r(o[j][0] * s0), tf32r(o[j][1] * s0));
            *(float2*)(Pwp + (g + 8) * PSP + j*8 + 2*t) =
                make_float2(tf32r(o[j][2] * s1), tf32r(o[j][3] * s1));
        }
        __syncwarp();
        #pragma unroll
        for (int ks = 0; ks < 8; ks++)
            ldsm4(qa[ks][0], qa[ks][1], qa[ks][2], qa[ks][3], pfrag + ks*32);
    }
    __syncthreads();

    // PASS 2: retrieval (V = V)
    flash_pass(Vtin);

    float inv0 = 1.f / l0, inv1 = 1.f / l1;
    int r0 = q0 + w * 16 + g;
    float* Op = Out + base;
    #pragma unroll
    for (int j = 0; j < 8; j++) {
        *(float2*)&Op[(size_t)r0     * HDIM + j*8 + 2*t] =
            make_float2(tf32r(o[j][0] * inv0), tf32r(o[j][1] * inv0));
        *(float2*)&Op[(size_t)(r0+8) * HDIM + j*8 + 2*t] =
            make_float2(tf32r(o[j][2] * inv1), tf32r(o[j][3] * inv1));
    }
}

// ---------------------------------------------------------------------------
// Launch
// ---------------------------------------------------------------------------
extern "C" void kernel_launch(void* const* d_in, const int* in_sizes, int n_in,
                              void* d_out, int out_size)
{
    const float* data = (const float*)d_in[0];
    const float* gk   = (const float*)d_in[1];
    const float* bk   = (const float*)d_in[2];
    const float* gq   = (const float*)d_in[3];
    const float* bq   = (const float*)d_in[4];
    const float* gv   = (const float*)d_in[5];
    const float* bv   = (const float*)d_in[6];
    const float* Wq   = (const float*)d_in[7];
    const float* bq2  = (const float*)d_in[8];
    const float* Wk   = (const float*)d_in[9];
    const float* bk2  = (const float*)d_in[10];
    const float* Wv   = (const float*)d_in[11];
    const float* bv2  = (const float*)d_in[12];
    const float* Wo   = (const float*)d_in[13];
    const float* bo   = (const float*)d_in[14];
    float* out = (float*)d_out;

    float *xq, *xk, *xv, *Q, *K, *Kt, *Vt, *O, *rWq, *rWk, *rWv, *rWo;
    cudaGetSymbolAddress((void**)&xq, g_xq);
    cudaGetSymbolAddress((void**)&xk, g_xk);
    cudaGetSymbolAddress((void**)&xv, g_xv);
    cudaGetSymbolAddress((void**)&Q,  g_Q);
    cudaGetSymbolAddress((void**)&K,  g_K);
    cudaGetSymbolAddress((void**)&Kt, g_Kt);
    cudaGetSymbolAddress((void**)&Vt, g_Vt);
    cudaGetSymbolAddress((void**)&O,  g_O);
    cudaGetSymbolAddress((void**)&rWq, g_Wq);
    cudaGetSymbolAddress((void**)&rWk, g_Wk);
    cudaGetSymbolAddress((void**)&rWv, g_Wv);
    cudaGetSymbolAddress((void**)&rWo, g_Wo);

    static int attr_done = 0;
    if (!attr_done) {
        cudaFuncSetAttribute(attn_fused, cudaFuncAttributeMaxDynamicSharedMemorySize, ATTN_SMEM);
        attr_done = 1;
    }

    dim3 rwgrid(DD / 32, DD / 32, 4);
    dim3 rwblk(32, 8);
    roundw_t<<<rwgrid, rwblk>>>(Wq, Wk, Wv, Wo, rWq, rWk, rWv, rWo);

    ln3_kernel<<<TOK, 256>>>(data, gk, bk, gq, bq, gv, bv, xq, xk, xv);

    dim3 qkvgrid(DD / 128, TOK / 128, 3);       // (8, 32, 3)
    gemm_qkv<<<qkvgrid, 256>>>(xq, xk, xv, rWq, rWk, rWv, bq2, bk2, bv2, Q, K, Kt, Vt);

    dim3 agrid(SS / 128, BB * HH);              // (16, 32)
    attn_fused<<<agrid, 256, ATTN_SMEM>>>(Q, K, Kt, Vt, O);

    dim3 ogrid(DD / 128, TOK / 128);            // (8, 32)
    gemm_out<<<ogrid, 256>>>(O, rWo, bo, out);
}

// round 9
// speedup vs baseline: 1.0424x; 1.0424x over previous
#include <cuda_runtime.h>
#include <math.h>

// Problem constants
#define BB   2
#define SS   2048
#define DD   1024
#define HH   16
#define HDIM 64
#define TOK  (BB*SS)           // 4096 rows
#define NSCALE 0.125f          // 1/sqrt(64)
#define LOG2E  1.4426950408889634f

// ---------------------------------------------------------------------------
// Scratch (static __device__ arrays; no allocation allowed)
// ---------------------------------------------------------------------------
__device__ float g_xq[TOK*DD];
__device__ float g_xk[TOK*DD];
__device__ float g_xv[TOK*DD];
__device__ float g_Q [TOK*DD];   // head layout [B,H,S,HD]
__device__ float g_K [TOK*DD];
__device__ float g_V [TOK*DD];
__device__ float g_Kt[TOK*DD];   // transposed [B,H,HD,S]
__device__ float g_Vt[TOK*DD];
__device__ float g_O [TOK*DD];
__device__ float g_Wq[DD*DD];    // tf32-rounded, TRANSPOSED [n][k]
__device__ float g_Wk[DD*DD];
__device__ float g_Wv[DD*DD];
__device__ float g_Wo[DD*DD];

// ---------------------------------------------------------------------------
// helpers
// ---------------------------------------------------------------------------
__device__ __forceinline__ float tf32r(float x) {
    unsigned u;
    asm("cvt.rna.tf32.f32 %0, %1;" : "=r"(u) : "f"(x));
    return __uint_as_float(u);
}
__device__ __forceinline__ float ex2(float x) {
    float y;
    asm("ex2.approx.ftz.f32 %0, %1;" : "=f"(y) : "f"(x));
    return y;
}
__device__ __forceinline__ void mma8(float* d, const unsigned* a, unsigned b0, unsigned b1) {
    asm volatile(
        "mma.sync.aligned.m16n8k8.row.col.f32.tf32.tf32.f32 "
        "{%0,%1,%2,%3}, {%4,%5,%6,%7}, {%8,%9}, {%0,%1,%2,%3};"
        : "+f"(d[0]), "+f"(d[1]), "+f"(d[2]), "+f"(d[3])
        : "r"(a[0]), "r"(a[1]), "r"(a[2]), "r"(a[3]), "r"(b0), "r"(b1));
}
__device__ __forceinline__ void ldsm4(unsigned& r0, unsigned& r1, unsigned& r2, unsigned& r3,
                                      unsigned addr) {
    asm volatile("ldmatrix.sync.aligned.m8n8.x4.shared.b16 {%0,%1,%2,%3}, [%4];"
        : "=r"(r0), "=r"(r1), "=r"(r2), "=r"(r3) : "r"(addr));
}
__device__ __forceinline__ void cpa16(unsigned dst, const void* src) {
    asm volatile("cp.async.cg.shared.global [%0], [%1], 16;" :: "r"(dst), "l"(src));
}
__device__ __forceinline__ void cpa_commit() { asm volatile("cp.async.commit_group;"); }
__device__ __forceinline__ void cpa_wait0()  { asm volatile("cp.async.wait_group 0;"); }
__device__ __forceinline__ void cpa_wait1()  { asm volatile("cp.async.wait_group 1;"); }

// ---------------------------------------------------------------------------
// Weight pre-round + transpose: dst[n][k] = tf32(src[k][n])
// ---------------------------------------------------------------------------
__global__ __launch_bounds__(256) void roundw_t(
    const float* __restrict__ w0, const float* __restrict__ w1,
    const float* __restrict__ w2, const float* __restrict__ w3,
    float* __restrict__ d0, float* __restrict__ d1,
    float* __restrict__ d2, float* __restrict__ d3)
{
    __shared__ float tile[32][33];
    const float* src; float* dst;
    switch (blockIdx.z) {
        case 0: src = w0; dst = d0; break;
        case 1: src = w1; dst = d1; break;
        case 2: src = w2; dst = d2; break;
        default: src = w3; dst = d3; break;
    }
    int k0 = blockIdx.x * 32, n0 = blockIdx.y * 32;
    int x = threadIdx.x;
    #pragma unroll
    for (int r = threadIdx.y; r < 32; r += 8)
        tile[r][x] = src[(size_t)(k0 + r) * DD + n0 + x];
    __syncthreads();
    #pragma unroll
    for (int r = threadIdx.y; r < 32; r += 8)
        dst[(size_t)(n0 + r) * DD + k0 + x] = tf32r(tile[x][r]);
}

// ---------------------------------------------------------------------------
// Per-head transpose: [B,H,S,HD] -> [B,H,HD,S]; two tensors in one launch.
// ---------------------------------------------------------------------------
__global__ __launch_bounds__(256) void transpose_both(
    const float* __restrict__ srcA, float* __restrict__ dstA,
    const float* __restrict__ srcB, float* __restrict__ dstB)
{
    __shared__ float tile[32][33];
    int z  = blockIdx.z;
    int bh = z & (BB*HH - 1);
    const float* src = (z < BB*HH) ? srcA : srcB;
    float*       dst = (z < BB*HH) ? dstA : dstB;
    int s0 = blockIdx.x * 32, h0 = blockIdx.y * 32;
    const float* S_ = src + (size_t)bh * SS * HDIM;
    float* D_ = dst + (size_t)bh * SS * HDIM;
    int x = threadIdx.x;
    #pragma unroll
    for (int r = threadIdx.y; r < 32; r += 8)
        tile[r][x] = S_[(size_t)(s0 + r) * HDIM + h0 + x];
    __syncthreads();
    #pragma unroll
    for (int r = threadIdx.y; r < 32; r += 8)
        D_[(size_t)(h0 + r) * SS + s0 + x] = tile[x][r];
}

// ---------------------------------------------------------------------------
// Block reduction (256 threads)
// ---------------------------------------------------------------------------
__device__ __forceinline__ float blk_sum256(float v) {
    __shared__ float red[8];
    int lane = threadIdx.x & 31;
    int w    = threadIdx.x >> 5;
    #pragma unroll
    for (int o = 16; o > 0; o >>= 1) v += __shfl_xor_sync(0xffffffffu, v, o);
    __syncthreads();
    if (lane == 0) red[w] = v;
    __syncthreads();
    return red[0]+red[1]+red[2]+red[3]+red[4]+red[5]+red[6]+red[7];
}

// ---------------------------------------------------------------------------
// Fused triple LayerNorm (outputs tf32-rounded)
// ---------------------------------------------------------------------------
__global__ __launch_bounds__(256) void ln3_kernel(
    const float* __restrict__ data,
    const float* __restrict__ gk, const float* __restrict__ bk,
    const float* __restrict__ gq, const float* __restrict__ bq,
    const float* __restrict__ gv, const float* __restrict__ bv,
    float* __restrict__ xq, float* __restrict__ xk, float* __restrict__ xv)
{
    int row = blockIdx.x;
    int t   = threadIdx.x;
    const float4 x4 = ((const float4*)(data + (size_t)row * DD))[t];
    float s = x4.x + x4.y + x4.z + x4.w;
    float mean = blk_sum256(s) * (1.0f / DD);
    float d0 = x4.x - mean, d1 = x4.y - mean, d2 = x4.z - mean, d3 = x4.w - mean;
    float sq = d0*d0 + d1*d1 + d2*d2 + d3*d3;
    float var = blk_sum256(sq) * (1.0f / DD);
    float r = rsqrtf(var + 1e-5f);
    float n0 = d0*r, n1 = d1*r, n2 = d2*r, n3 = d3*r;

    float4 g4, b4, o4;
    size_t base = (size_t)row * DD;

    g4 = ((const float4*)gq)[t]; b4 = ((const float4*)bq)[t];
    o4 = make_float4(tf32r(n0*g4.x + b4.x), tf32r(n1*g4.y + b4.y),
                     tf32r(n2*g4.z + b4.z), tf32r(n3*g4.w + b4.w));
    ((float4*)(xq + base))[t] = o4;

    g4 = ((const float4*)gk)[t]; b4 = ((const float4*)bk)[t];
    o4 = make_float4(tf32r(n0*g4.x + b4.x), tf32r(n1*g4.y + b4.y),
                     tf32r(n2*g4.z + b4.z), tf32r(n3*g4.w + b4.w));
    ((float4*)(xk + base))[t] = o4;

    g4 = ((const float4*)gv)[t]; b4 = ((const float4*)bv)[t];
    o4 = make_float4(tf32r(n0*g4.x + b4.x), tf32r(n1*g4.y + b4.y),
                     tf32r(n2*g4.z + b4.z), tf32r(n3*g4.w + b4.w));
    ((float4*)(xv + base))[t] = o4;
}

// ---------------------------------------------------------------------------
// tf32 GEMM body (mma.sync + ldmatrix), cp.async double-buffered, BK=32.
// A [M,K] (or head-layout gather), W TRANSPOSED [N,K].
// MODE_OUT: 0 row-major | 1 head layout
// ---------------------------------------------------------------------------
template<int MODE_IN, int MODE_OUT, int ROUND>
__device__ __forceinline__ void gemm_body(
    const float* __restrict__ A, const float* __restrict__ Wt,
    const float* __restrict__ bias, float* __restrict__ C)
{
    constexpr int BM = 128, BK = 32;
    constexpr int PITCH = 36;
    constexpr int TSZ = BM * PITCH;
    __shared__ float As[2 * TSZ];
    __shared__ float Bs[2 * TSZ];

    int tid  = threadIdx.x;
    int lane = tid & 31;
    int w    = tid >> 5;
    int g    = lane >> 2;
    int t    = lane & 3;
    int wm   = (w >> 2) * 64;
    int wn   = (w & 3) * 32;
    int bm   = blockIdx.y * BM;
    int bn   = blockIdx.x * BM;

    int lr = tid >> 1;
    int lc = (tid & 1) * 16;

    unsigned as_base = (unsigned)__cvta_generic_to_shared(As);
    unsigned bs_base = (unsigned)__cvta_generic_to_shared(Bs);

    unsigned a_ld = as_base + (((lane & 15) * PITCH + (lane >> 4) * 4) * 4);
    unsigned b_ld = bs_base + (((lane & 7)  * PITCH + (lane >> 3) * 4) * 4);

    float acc[4][4][4];
    #pragma unroll
    for (int i = 0; i < 4; i++)
        #pragma unroll
        for (int j = 0; j < 4; j++)
            #pragma unroll
            for (int q = 0; q < 4; q++) acc[i][j][q] = 0.f;

    auto load_tile = [&](int it, int stg) {
        int kk = it * BK;
        int gm = bm + lr;
        int gk = kk + lc;
        const float* pa;
        if (MODE_IN == 0) {
            pa = &A[(size_t)gm * DD + gk];
        } else {
            int b  = gm >> 11, s2 = gm & (SS - 1);
            int h  = gk >> 6,  hd = gk & (HDIM - 1);
            pa = &A[(((size_t)(b*HH + h) * SS + s2) * HDIM) + hd];
        }
        unsigned da = as_base + (stg * TSZ + lr * PITCH + lc) * 4;
        #pragma unroll
        for (int i = 0; i < 4; i++) cpa16(da + i*16, pa + i*4);
        const float* pb = &Wt[(size_t)(bn + lr) * DD + kk + lc];
        unsigned db = bs_base + (stg * TSZ + lr * PITCH + lc) * 4;
        #pragma unroll
        for (int i = 0; i < 4; i++) cpa16(db + i*16, pb + i*4);
    };

    constexpr int KITER = DD / BK;
    load_tile(0, 0);
    cpa_commit();

    for (int it = 0; it < KITER; it++) {
        int cur = it & 1;
        if (it + 1 < KITER) {
            load_tile(it + 1, cur ^ 1);
            cpa_commit();
            cpa_wait1();
        } else {
            cpa_wait0();
        }
        __syncthreads();

        unsigned ab = a_ld + cur * TSZ * 4;
        unsigned bb = b_ld + cur * TSZ * 4;

        #pragma unroll
        for (int kh = 0; kh < 2; kh++) {
            unsigned bf[4][4];
            #pragma unroll
            for (int ni = 0; ni < 4; ni++)
                ldsm4(bf[ni][0], bf[ni][1], bf[ni][2], bf[ni][3],
                      bb + ((wn + ni*8) * PITCH + kh*16) * 4);
            #pragma unroll
            for (int kp = 0; kp < 2; kp++) {
                int k0 = kh*16 + kp*8;
                unsigned af[4][4];
                #pragma unroll
                for (int mi = 0; mi < 4; mi++)
                    ldsm4(af[mi][0], af[mi][1], af[mi][2], af[mi][3],
                          ab + ((wm + mi*16) * PITCH + k0) * 4);
                #pragma unroll
                for (int mi = 0; mi < 4; mi++)
                    #pragma unroll
                    for (int ni = 0; ni < 4; ni++)
                        mma8(acc[mi][ni], af[mi], bf[ni][2*kp], bf[ni][2*kp + 1]);
            }
        }
        __syncthreads();
    }

    #pragma unroll
    for (int mi = 0; mi < 4; mi++) {
        #pragma unroll
        for (int ni = 0; ni < 4; ni++) {
            int row = bm + wm + mi * 16 + g;
            int col = bn + wn + ni * 8 + 2 * t;
            float2 bia = *(const float2*)&bias[col];
            float2 v0, v1;
            if (ROUND) {
                v0 = make_float2(tf32r(acc[mi][ni][0] + bia.x), tf32r(acc[mi][ni][1] + bia.y));
                v1 = make_float2(tf32r(acc[mi][ni][2] + bia.x), tf32r(acc[mi][ni][3] + bia.y));
            } else {
                v0 = make_float2(acc[mi][ni][0] + bia.x, acc[mi][ni][1] + bia.y);
                v1 = make_float2(acc[mi][ni][2] + bia.x, acc[mi][ni][3] + bia.y);
            }
            if (MODE_OUT == 0) {
                *(float2*)&C[(size_t)row * DD + col]       = v0;
                *(float2*)&C[(size_t)(row + 8) * DD + col] = v1;
            } else {
                int h = col >> 6, hd = col & (HDIM - 1);
                int b0i = row >> 11,       s0 = row & (SS - 1);
                int b1i = (row + 8) >> 11, s1 = (row + 8) & (SS - 1);
                *(float2*)&C[((size_t)(b0i*HH + h) * SS + s0) * HDIM + hd] = v0;
                *(float2*)&C[((size_t)(b1i*HH + h) * SS + s1) * HDIM + hd] = v1;
            }
        }
    }
}

__global__ __launch_bounds__(256, 2) void gemm_qkv(
    const float* __restrict__ xq, const float* __restrict__ xk, const float* __restrict__ xv,
    const float* __restrict__ Wq, const float* __restrict__ Wk, const float* __restrict__ Wv,
    const float* __restrict__ bq, const float* __restrict__ bk, const float* __restrict__ bv,
    float* __restrict__ Q, float* __restrict__ K, float* __restrict__ V)
{
    if (blockIdx.z == 0)      gemm_body<0, 1, 1>(xq, Wq, bq, Q);
    else if (blockIdx.z == 1) gemm_body<0, 1, 1>(xk, Wk, bk, K);
    else                      gemm_body<0, 1, 1>(xv, Wv, bv, V);
}

__global__ __launch_bounds__(256, 2) void gemm_out(
    const float* __restrict__ A, const float* __restrict__ Wt,
    const float* __restrict__ bias, float* __restrict__ C)
{
    gemm_body<1, 0, 0>(A, Wt, bias, C);
}

// ---------------------------------------------------------------------------
// FUSED double-pass flash attention (mma.sync), register-pressure-tuned.
//   pass 1: Q2 = softmax(b Q K^T) K      (V^T tile source = Kt)
//   pass 2: O  = softmax(b Q2 K^T) V     (V^T tile source = Vt)
// 256 threads = 8 warps; CTA = 128 queries (16/warp); K-tile 64 keys.
// ---------------------------------------------------------------------------
#define TSP 68
#define PSP 68
#define TILESZ (64*TSP)
#define ATTN_SMEM ((4*TILESZ + 8*16*PSP) * 4)

__global__ __launch_bounds__(256, 2) void attn_fused(
    const float* __restrict__ Qin, const float* __restrict__ Kin,
    const float* __restrict__ Ktin, const float* __restrict__ Vtin,
    float* __restrict__ Out)
{
    extern __shared__ float sm[];
    float* Ks = sm;                 // [2][64][TSP]  keys x hd
    float* Ts = sm + 2 * TILESZ;    // [2][64][TSP]  hd x keys (V^T tile)
    float* Ps = sm + 4 * TILESZ;    // [8][16][PSP]
    unsigned ks_base = (unsigned)__cvta_generic_to_shared(Ks);
    unsigned ts_base = (unsigned)__cvta_generic_to_shared(Ts);
    unsigned ps_base = (unsigned)__cvta_generic_to_shared(Ps);

    int tid  = threadIdx.x;
    int lane = tid & 31;
    int w    = tid >> 5;
    int g    = lane >> 2;
    int t    = lane & 3;
    int bh   = blockIdx.y;
    int q0   = blockIdx.x * 128;
    size_t base = (size_t)bh * SS * HDIM;

    const float QS = NSCALE * LOG2E;

    int lrow = tid >> 2;          // 0..63
    int lcol = (tid & 3) * 16;    // 0,16,32,48

    unsigned kfrag = ks_base + (((lane & 7) * TSP + (lane >> 3) * 4) * 4);
    unsigned tfrag = ts_base + (((lane & 7) * TSP + (lane >> 3) * 4) * 4);
    float*   Pwp   = Ps + w * 16 * PSP;
    unsigned pfrag = ps_base + ((w * 16 * PSP +
                     (((lane >> 3) & 1) * 8 + (lane & 7)) * PSP + (lane >> 4) * 4) * 4);

    unsigned qa[8][4];
    {
        const float* Qp = Qin + base;
        int r0 = q0 + w * 16 + g;
        #pragma unroll
        for (int ks = 0; ks < 8; ks++) {
            qa[ks][0] = __float_as_uint(tf32r(Qp[(size_t)r0     * HDIM + ks*8 + t    ] * QS));
            qa[ks][1] = __float_as_uint(tf32r(Qp[(size_t)(r0+8) * HDIM + ks*8 + t    ] * QS));
            qa[ks][2] = __float_as_uint(tf32r(Qp[(size_t)r0     * HDIM + ks*8 + t + 4] * QS));
            qa[ks][3] = __float_as_uint(tf32r(Qp[(size_t)(r0+8) * HDIM + ks*8 + t + 4] * QS));
        }
    }

    float o[8][4];
    float l0, l1;
    constexpr int NT = SS / 64;   // 32

    auto flash_pass = [&](const float* __restrict__ Tsrc) {
        #pragma unroll
        for (int j = 0; j < 8; j++)
            #pragma unroll
            for (int q = 0; q < 4; q++) o[j][q] = 0.f;
        l0 = 0.f; l1 = 0.f;

        auto load_kv = [&](int kt, int stg) {
            const float* Kp = Kin  + base + (size_t)(kt*64 + lrow) * HDIM + lcol;
            const float* Tp = Tsrc + base + (size_t)lrow * SS + kt*64 + lcol;
            unsigned kd = ks_base + (stg * TILESZ + lrow * TSP + lcol) * 4;
            unsigned td = ts_base + (stg * TILESZ + lrow * TSP + lcol) * 4;
            #pragma unroll
            for (int i = 0; i < 4; i++) cpa16(kd + i*16, Kp + i*4);
            #pragma unroll
            for (int i = 0; i < 4; i++) cpa16(td + i*16, Tp + i*4);
        };

        load_kv(0, 0);
        cpa_commit();

        for (int kt = 0; kt < NT; kt++) {
            int cur = kt & 1;
            if (kt + 1 < NT) {
                load_kv(kt + 1, cur ^ 1);
                cpa_commit();
                cpa_wait1();
            } else {
                cpa_wait0();
            }
            __syncthreads();

            unsigned kf = kfrag + cur * TILESZ * 4;
            unsigned tf = tfrag + cur * TILESZ * 4;

            // S = Q K^T, p = 2^S, store P  (s transient: 4 regs per n)
            #pragma unroll
            for (int n = 0; n < 8; n++) {
                float sa[4] = {0.f, 0.f, 0.f, 0.f};
                #pragma unroll
                for (int cp = 0; cp < 4; cp++) {
                    unsigned b0, b1, b2, b3;
                    ldsm4(b0, b1, b2, b3, kf + (n*8*TSP + cp*16) * 4);
                    mma8(sa, qa[2*cp    ], b0, b1);
                    mma8(sa, qa[2*cp + 1], b2, b3);
                }
                float p0 = ex2(sa[0]), p1 = ex2(sa[1]);
                float p2 = ex2(sa[2]), p3 = ex2(sa[3]);
                l0 += p0 + p1;
                l1 += p2 + p3;
                *(float2*)(Pwp +  g      * PSP + n*8 + 2*t) = make_float2(tf32r(p0), tf32r(p1));
                *(float2*)(Pwp + (g + 8) * PSP + n*8 + 2*t) = make_float2(tf32r(p2), tf32r(p3));
            }
            __syncwarp();

            // O += P V — cp outer so only ONE pa pair (8 regs) is live at a
            // time (was pa[8][4]=32 regs -> register spills at the 128 cap).
            // Per-o[j] accumulation order over cp is unchanged (bitwise same).
            #pragma unroll
            for (int cp = 0; cp < 4; cp++) {
                unsigned pa0[4], pa1[4];
                ldsm4(pa0[0], pa0[1], pa0[2], pa0[3], pfrag + (2*cp    )*32);
                ldsm4(pa1[0], pa1[1], pa1[2], pa1[3], pfrag + (2*cp + 1)*32);
                #pragma unroll
                for (int j = 0; j < 8; j++) {
                    unsigned v0, v1, v2, v3;
                    ldsm4(v0, v1, v2, v3, tf + (j*8*TSP + cp*16) * 4);
                    mma8(o[j], pa0, v0, v1);
                    mma8(o[j], pa1, v2, v3);
                }
            }
            __syncthreads();
        }

        l0 += __shfl_xor_sync(0xffffffffu, l0, 1);
        l0 += __shfl_xor_sync(0xffffffffu, l0, 2);
        l1 += __shfl_xor_sync(0xffffffffu, l1, 1);
        l1 += __shfl_xor_sync(0xffffffffu, l1, 2);
    };

    // PASS 1: Hopfield update (V = K)
    flash_pass(Ktin);

    // Q2 = O/l rescaled by QS; round, store to P region, reload as a-frags.
    {
        float s0 = QS / l0, s1 = QS / l1;
        #pragma unroll
        for (int j = 0; j < 8; j++) {
            *(float2*)(Pwp +  g      * PSP + j*8 + 2*t) =
                make_float2(tf32r(o[j][0] * s0), tf32r(o[j][1] * s0));
            *(float2*)(Pwp + (g + 8) * PSP + j*8 + 2*t) =
                make_float2(tf32r(o[j][2] * s1), tf32r(o[j][3] * s1));
        }
        __syncwarp();
        #pragma unroll
        for (int ks = 0; ks < 8; ks++)
            ldsm4(qa[ks][0], qa[ks][1], qa[ks][2], qa[ks][3], pfrag + ks*32);
    }
    __syncthreads();

    // PASS 2: retrieval (V = V)
    flash_pass(Vtin);

    float inv0 = 1.f / l0, inv1 = 1.f / l1;
    int r0 = q0 + w * 16 + g;
    float* Op = Out + base;
    #pragma unroll
    for (int j = 0; j < 8; j++) {
        *(float2*)&Op[(size_t)r0     * HDIM + j*8 + 2*t] =
            make_float2(tf32r(o[j][0] * inv0), tf32r(o[j][1] * inv0));
        *(float2*)&Op[(size_t)(r0+8) * HDIM + j*8 + 2*t] =
            make_float2(tf32r(o[j][2] * inv1), tf32r(o[j][3] * inv1));
    }
}

// ---------------------------------------------------------------------------
// Launch
// ---------------------------------------------------------------------------
extern "C" void kernel_launch(void* const* d_in, const int* in_sizes, int n_in,
                              void* d_out, int out_size)
{
    const float* data = (const float*)d_in[0];
    const float* gk   = (const float*)d_in[1];
    const float* bk   = (const float*)d_in[2];
    const float* gq   = (const float*)d_in[3];
    const float* bq   = (const float*)d_in[4];
    const float* gv   = (const float*)d_in[5];
    const float* bv   = (const float*)d_in[6];
    const float* Wq   = (const float*)d_in[7];
    const float* bq2  = (const float*)d_in[8];
    const float* Wk   = (const float*)d_in[9];
    const float* bk2  = (const float*)d_in[10];
    const float* Wv   = (const float*)d_in[11];
    const float* bv2  = (const float*)d_in[12];
    const float* Wo   = (const float*)d_in[13];
    const float* bo   = (const float*)d_in[14];
    float* out = (float*)d_out;

    float *xq, *xk, *xv, *Q, *K, *V, *Kt, *Vt, *O, *rWq, *rWk, *rWv, *rWo;
    cudaGetSymbolAddress((void**)&xq, g_xq);
    cudaGetSymbolAddress((void**)&xk, g_xk);
    cudaGetSymbolAddress((void**)&xv, g_xv);
    cudaGetSymbolAddress((void**)&Q,  g_Q);
    cudaGetSymbolAddress((void**)&K,  g_K);
    cudaGetSymbolAddress((void**)&V,  g_V);
    cudaGetSymbolAddress((void**)&Kt, g_Kt);
    cudaGetSymbolAddress((void**)&Vt, g_Vt);
    cudaGetSymbolAddress((void**)&O,  g_O);
    cudaGetSymbolAddress((void**)&rWq, g_Wq);
    cudaGetSymbolAddress((void**)&rWk, g_Wk);
    cudaGetSymbolAddress((void**)&rWv, g_Wv);
    cudaGetSymbolAddress((void**)&rWo, g_Wo);

    static int attr_done = 0;
    if (!attr_done) {
        cudaFuncSetAttribute(attn_fused, cudaFuncAttributeMaxDynamicSharedMemorySize, ATTN_SMEM);
        attr_done = 1;
    }

    dim3 rwgrid(DD / 32, DD / 32, 4);
    dim3 rwblk(32, 8);
    roundw_t<<<rwgrid, rwblk>>>(Wq, Wk, Wv, Wo, rWq, rWk, rWv, rWo);

    ln3_kernel<<<TOK, 256>>>(data, gk, bk, gq, bq, gv, bv, xq, xk, xv);

    dim3 qkvgrid(DD / 128, TOK / 128, 3);       // (8, 32, 3)
    gemm_qkv<<<qkvgrid, 256>>>(xq, xk, xv, rWq, rWk, rWv, bq2, bk2, bv2, Q, K, V);

    dim3 tgrid(SS / 32, HDIM / 32, 2 * BB * HH);
    dim3 tblk(32, 8);
    transpose_both<<<tgrid, tblk>>>(K, Kt, V, Vt);

    dim3 agrid(SS / 128, BB * HH);              // (16, 32)
    attn_fused<<<agrid, 256, ATTN_SMEM>>>(Q, K, Kt, Vt, O);

    dim3 ogrid(DD / 128, TOK / 128);
    gemm_out<<<ogrid, 256>>>(O, rWo, bo, out);
}

// round 10
// speedup vs baseline: 1.0544x; 1.0115x over previous
#include <cuda_runtime.h>
#include <math.h>

// Problem constants
#define BB   2
#define SS   2048
#define DD   1024
#define HH   16
#define HDIM 64
#define TOK  (BB*SS)           // 4096 rows
#define NSCALE 0.125f          // 1/sqrt(64)
#define LOG2E  1.4426950408889634f

// ---------------------------------------------------------------------------
// Scratch (static __device__ arrays; no allocation allowed)
// ---------------------------------------------------------------------------
__device__ float g_xq[TOK*DD];
__device__ float g_xk[TOK*DD];
__device__ float g_xv[TOK*DD];
__device__ float g_Q [TOK*DD];   // head layout [B,H,S,HD]
__device__ float g_K [TOK*DD];
__device__ float g_V [TOK*DD];
__device__ float g_Kt[TOK*DD];   // transposed [B,H,HD,S]
__device__ float g_Vt[TOK*DD];
__device__ float g_O [TOK*DD];
__device__ float g_Wq[DD*DD];    // tf32-rounded, TRANSPOSED [n][k]
__device__ float g_Wk[DD*DD];
__device__ float g_Wv[DD*DD];
__device__ float g_Wo[DD*DD];

// ---------------------------------------------------------------------------
// helpers
// ---------------------------------------------------------------------------
__device__ __forceinline__ float tf32r(float x) {
    unsigned u;
    asm("cvt.rna.tf32.f32 %0, %1;" : "=r"(u) : "f"(x));
    return __uint_as_float(u);
}
__device__ __forceinline__ float ex2(float x) {
    float y;
    asm("ex2.approx.ftz.f32 %0, %1;" : "=f"(y) : "f"(x));
    return y;
}
__device__ __forceinline__ void mma8(float* d, const unsigned* a, unsigned b0, unsigned b1) {
    asm volatile(
        "mma.sync.aligned.m16n8k8.row.col.f32.tf32.tf32.f32 "
        "{%0,%1,%2,%3}, {%4,%5,%6,%7}, {%8,%9}, {%0,%1,%2,%3};"
        : "+f"(d[0]), "+f"(d[1]), "+f"(d[2]), "+f"(d[3])
        : "r"(a[0]), "r"(a[1]), "r"(a[2]), "r"(a[3]), "r"(b0), "r"(b1));
}
__device__ __forceinline__ void ldsm4(unsigned& r0, unsigned& r1, unsigned& r2, unsigned& r3,
                                      unsigned addr) {
    asm volatile("ldmatrix.sync.aligned.m8n8.x4.shared.b16 {%0,%1,%2,%3}, [%4];"
        : "=r"(r0), "=r"(r1), "=r"(r2), "=r"(r3) : "r"(addr));
}
__device__ __forceinline__ void cpa16(unsigned dst, const void* src) {
    asm volatile("cp.async.cg.shared.global [%0], [%1], 16;" :: "r"(dst), "l"(src));
}
__device__ __forceinline__ void cpa_commit() { asm volatile("cp.async.commit_group;"); }
__device__ __forceinline__ void cpa_wait0()  { asm volatile("cp.async.wait_group 0;"); }
__device__ __forceinline__ void cpa_wait1()  { asm volatile("cp.async.wait_group 1;"); }

// ---------------------------------------------------------------------------
// Weight pre-round + transpose: dst[n][k] = tf32(src[k][n])
// ---------------------------------------------------------------------------
__global__ __launch_bounds__(256) void roundw_t(
    const float* __restrict__ w0, const float* __restrict__ w1,
    const float* __restrict__ w2, const float* __restrict__ w3,
    float* __restrict__ d0, float* __restrict__ d1,
    float* __restrict__ d2, float* __restrict__ d3)
{
    __shared__ float tile[32][33];
    const float* src; float* dst;
    switch (blockIdx.z) {
        case 0: src = w0; dst = d0; break;
        case 1: src = w1; dst = d1; break;
        case 2: src = w2; dst = d2; break;
        default: src = w3; dst = d3; break;
    }
    int k0 = blockIdx.x * 32, n0 = blockIdx.y * 32;
    int x = threadIdx.x;
    #pragma unroll
    for (int r = threadIdx.y; r < 32; r += 8)
        tile[r][x] = src[(size_t)(k0 + r) * DD + n0 + x];
    __syncthreads();
    #pragma unroll
    for (int r = threadIdx.y; r < 32; r += 8)
        dst[(size_t)(n0 + r) * DD + k0 + x] = tf32r(tile[x][r]);
}

// ---------------------------------------------------------------------------
// Per-head transpose: [B,H,S,HD] -> [B,H,HD,S]; two tensors in one launch.
// ---------------------------------------------------------------------------
__global__ __launch_bounds__(256) void transpose_both(
    const float* __restrict__ srcA, float* __restrict__ dstA,
    const float* __restrict__ srcB, float* __restrict__ dstB)
{
    __shared__ float tile[32][33];
    int z  = blockIdx.z;
    int bh = z & (BB*HH - 1);
    const float* src = (z < BB*HH) ? srcA : srcB;
    float*       dst = (z < BB*HH) ? dstA : dstB;
    int s0 = blockIdx.x * 32, h0 = blockIdx.y * 32;
    const float* S_ = src + (size_t)bh * SS * HDIM;
    float* D_ = dst + (size_t)bh * SS * HDIM;
    int x = threadIdx.x;
    #pragma unroll
    for (int r = threadIdx.y; r < 32; r += 8)
        tile[r][x] = S_[(size_t)(s0 + r) * HDIM + h0 + x];
    __syncthreads();
    #pragma unroll
    for (int r = threadIdx.y; r < 32; r += 8)
        D_[(size_t)(h0 + r) * SS + s0 + x] = tile[x][r];
}

// ---------------------------------------------------------------------------
// Block reduction (256 threads)
// ---------------------------------------------------------------------------
__device__ __forceinline__ float blk_sum256(float v) {
    __shared__ float red[8];
    int lane = threadIdx.x & 31;
    int w    = threadIdx.x >> 5;
    #pragma unroll
    for (int o = 16; o > 0; o >>= 1) v += __shfl_xor_sync(0xffffffffu, v, o);
    __syncthreads();
    if (lane == 0) red[w] = v;
    __syncthreads();
    return red[0]+red[1]+red[2]+red[3]+red[4]+red[5]+red[6]+red[7];
}

// ---------------------------------------------------------------------------
// Fused triple LayerNorm (outputs tf32-rounded)
// ---------------------------------------------------------------------------
__global__ __launch_bounds__(256) void ln3_kernel(
    const float* __restrict__ data,
    const float* __restrict__ gk, const float* __restrict__ bk,
    const float* __restrict__ gq, const float* __restrict__ bq,
    const float* __restrict__ gv, const float* __restrict__ bv,
    float* __restrict__ xq, float* __restrict__ xk, float* __restrict__ xv)
{
    int row = blockIdx.x;
    int t   = threadIdx.x;
    const float4 x4 = ((const float4*)(data + (size_t)row * DD))[t];
    float s = x4.x + x4.y + x4.z + x4.w;
    float mean = blk_sum256(s) * (1.0f / DD);
    float d0 = x4.x - mean, d1 = x4.y - mean, d2 = x4.z - mean, d3 = x4.w - mean;
    float sq = d0*d0 + d1*d1 + d2*d2 + d3*d3;
    float var = blk_sum256(sq) * (1.0f / DD);
    float r = rsqrtf(var + 1e-5f);
    float n0 = d0*r, n1 = d1*r, n2 = d2*r, n3 = d3*r;

    float4 g4, b4, o4;
    size_t base = (size_t)row * DD;

    g4 = ((const float4*)gq)[t]; b4 = ((const float4*)bq)[t];
    o4 = make_float4(tf32r(n0*g4.x + b4.x), tf32r(n1*g4.y + b4.y),
                     tf32r(n2*g4.z + b4.z), tf32r(n3*g4.w + b4.w));
    ((float4*)(xq + base))[t] = o4;

    g4 = ((const float4*)gk)[t]; b4 = ((const float4*)bk)[t];
    o4 = make_float4(tf32r(n0*g4.x + b4.x), tf32r(n1*g4.y + b4.y),
                     tf32r(n2*g4.z + b4.z), tf32r(n3*g4.w + b4.w));
    ((float4*)(xk + base))[t] = o4;

    g4 = ((const float4*)gv)[t]; b4 = ((const float4*)bv)[t];
    o4 = make_float4(tf32r(n0*g4.x + b4.x), tf32r(n1*g4.y + b4.y),
                     tf32r(n2*g4.z + b4.z), tf32r(n3*g4.w + b4.w));
    ((float4*)(xv + base))[t] = o4;
}

// ---------------------------------------------------------------------------
// tf32 GEMM body (mma.sync + ldmatrix), cp.async double-buffered, BK=32.
// A [M,K] (or head-layout gather), W TRANSPOSED [N,K].
// MODE_OUT: 0 row-major | 1 head layout
// ---------------------------------------------------------------------------
template<int MODE_IN, int MODE_OUT, int ROUND>
__device__ __forceinline__ void gemm_body(
    const float* __restrict__ A, const float* __restrict__ Wt,
    const float* __restrict__ bias, float* __restrict__ C)
{
    constexpr int BM = 128, BK = 32;
    constexpr int PITCH = 36;
    constexpr int TSZ = BM * PITCH;
    __shared__ float As[2 * TSZ];
    __shared__ float Bs[2 * TSZ];

    int tid  = threadIdx.x;
    int lane = tid & 31;
    int w    = tid >> 5;
    int g    = lane >> 2;
    int t    = lane & 3;
    int wm   = (w >> 2) * 64;
    int wn   = (w & 3) * 32;
    int bm   = blockIdx.y * BM;
    int bn   = blockIdx.x * BM;

    int lr = tid >> 1;
    int lc = (tid & 1) * 16;

    unsigned as_base = (unsigned)__cvta_generic_to_shared(As);
    unsigned bs_base = (unsigned)__cvta_generic_to_shared(Bs);

    unsigned a_ld = as_base + (((lane & 15) * PITCH + (lane >> 4) * 4) * 4);
    unsigned b_ld = bs_base + (((lane & 7)  * PITCH + (lane >> 3) * 4) * 4);

    float acc[4][4][4];
    #pragma unroll
    for (int i = 0; i < 4; i++)
        #pragma unroll
        for (int j = 0; j < 4; j++)
            #pragma unroll
            for (int q = 0; q < 4; q++) acc[i][j][q] = 0.f;

    auto load_tile = [&](int it, int stg) {
        int kk = it * BK;
        int gm = bm + lr;
        int gk = kk + lc;
        const float* pa;
        if (MODE_IN == 0) {
            pa = &A[(size_t)gm * DD + gk];
        } else {
            int b  = gm >> 11, s2 = gm & (SS - 1);
            int h  = gk >> 6,  hd = gk & (HDIM - 1);
            pa = &A[(((size_t)(b*HH + h) * SS + s2) * HDIM) + hd];
        }
        unsigned da = as_base + (stg * TSZ + lr * PITCH + lc) * 4;
        #pragma unroll
        for (int i = 0; i < 4; i++) cpa16(da + i*16, pa + i*4);
        const float* pb = &Wt[(size_t)(bn + lr) * DD + kk + lc];
        unsigned db = bs_base + (stg * TSZ + lr * PITCH + lc) * 4;
        #pragma unroll
        for (int i = 0; i < 4; i++) cpa16(db + i*16, pb + i*4);
    };

    constexpr int KITER = DD / BK;
    load_tile(0, 0);
    cpa_commit();

    for (int it = 0; it < KITER; it++) {
        int cur = it & 1;
        if (it + 1 < KITER) {
            load_tile(it + 1, cur ^ 1);
            cpa_commit();
            cpa_wait1();
        } else {
            cpa_wait0();
        }
        __syncthreads();

        unsigned ab = a_ld + cur * TSZ * 4;
        unsigned bb = b_ld + cur * TSZ * 4;

        #pragma unroll
        for (int kh = 0; kh < 2; kh++) {
            unsigned bf[4][4];
            #pragma unroll
            for (int ni = 0; ni < 4; ni++)
                ldsm4(bf[ni][0], bf[ni][1], bf[ni][2], bf[ni][3],
                      bb + ((wn + ni*8) * PITCH + kh*16) * 4);
            #pragma unroll
            for (int kp = 0; kp < 2; kp++) {
                int k0 = kh*16 + kp*8;
                unsigned af[4][4];
                #pragma unroll
                for (int mi = 0; mi < 4; mi++)
                    ldsm4(af[mi][0], af[mi][1], af[mi][2], af[mi][3],
                          ab + ((wm + mi*16) * PITCH + k0) * 4);
                #pragma unroll
                for (int mi = 0; mi < 4; mi++)
                    #pragma unroll
                    for (int ni = 0; ni < 4; ni++)
                        mma8(acc[mi][ni], af[mi], bf[ni][2*kp], bf[ni][2*kp + 1]);
            }
        }
        __syncthreads();
    }

    #pragma unroll
    for (int mi = 0; mi < 4; mi++) {
        #pragma unroll
        for (int ni = 0; ni < 4; ni++) {
            int row = bm + wm + mi * 16 + g;
            int col = bn + wn + ni * 8 + 2 * t;
            float2 bia = *(const float2*)&bias[col];
            float2 v0, v1;
            if (ROUND) {
                v0 = make_float2(tf32r(acc[mi][ni][0] + bia.x), tf32r(acc[mi][ni][1] + bia.y));
                v1 = make_float2(tf32r(acc[mi][ni][2] + bia.x), tf32r(acc[mi][ni][3] + bia.y));
            } else {
                v0 = make_float2(acc[mi][ni][0] + bia.x, acc[mi][ni][1] + bia.y);
                v1 = make_float2(acc[mi][ni][2] + bia.x, acc[mi][ni][3] + bia.y);
            }
            if (MODE_OUT == 0) {
                *(float2*)&C[(size_t)row * DD + col]       = v0;
                *(float2*)&C[(size_t)(row + 8) * DD + col] = v1;
            } else {
                int h = col >> 6, hd = col & (HDIM - 1);
                int b0i = row >> 11,       s0 = row & (SS - 1);
                int b1i = (row + 8) >> 11, s1 = (row + 8) & (SS - 1);
                *(float2*)&C[((size_t)(b0i*HH + h) * SS + s0) * HDIM + hd] = v0;
                *(float2*)&C[((size_t)(b1i*HH + h) * SS + s1) * HDIM + hd] = v1;
            }
        }
    }
}

__global__ __launch_bounds__(256, 2) void gemm_qkv(
    const float* __restrict__ xq, const float* __restrict__ xk, const float* __restrict__ xv,
    const float* __restrict__ Wq, const float* __restrict__ Wk, const float* __restrict__ Wv,
    const float* __restrict__ bq, const float* __restrict__ bk, const float* __restrict__ bv,
    float* __restrict__ Q, float* __restrict__ K, float* __restrict__ V)
{
    if (blockIdx.z == 0)      gemm_body<0, 1, 1>(xq, Wq, bq, Q);
    else if (blockIdx.z == 1) gemm_body<0, 1, 1>(xk, Wk, bk, K);
    else                      gemm_body<0, 1, 1>(xv, Wv, bv, V);
}

__global__ __launch_bounds__(256, 2) void gemm_out(
    const float* __restrict__ A, const float* __restrict__ Wt,
    const float* __restrict__ bias, float* __restrict__ C)
{
    gemm_body<1, 0, 0>(A, Wt, bias, C);
}

// ---------------------------------------------------------------------------
// FUSED double-pass flash attention (mma.sync), key-group pipelined:
// per 16-key group i: softmax(i) overlapped with S-mma of group i+1,
// then P·V(i). Keeps the tensor pipe fed during MUFU/STS latency.
//   pass 1: Q2 = softmax(b Q K^T) K      (V^T tile source = Kt)
//   pass 2: O  = softmax(b Q2 K^T) V     (V^T tile source = Vt)
// 256 threads = 8 warps; CTA = 128 queries (16/warp); K-tile 64 keys.
// ---------------------------------------------------------------------------
#define TSP 68
#define PSP 68
#define TILESZ (64*TSP)
#define ATTN_SMEM ((4*TILESZ + 8*16*PSP) * 4)

__global__ __launch_bounds__(256, 2) void attn_fused(
    const float* __restrict__ Qin, const float* __restrict__ Kin,
    const float* __restrict__ Ktin, const float* __restrict__ Vtin,
    float* __restrict__ Out)
{
    extern __shared__ float sm[];
    float* Ks = sm;                 // [2][64][TSP]  keys x hd
    float* Ts = sm + 2 * TILESZ;    // [2][64][TSP]  hd x keys (V^T tile)
    float* Ps = sm + 4 * TILESZ;    // [8][16][PSP]
    unsigned ks_base = (unsigned)__cvta_generic_to_shared(Ks);
    unsigned ts_base = (unsigned)__cvta_generic_to_shared(Ts);
    unsigned ps_base = (unsigned)__cvta_generic_to_shared(Ps);

    int tid  = threadIdx.x;
    int lane = tid & 31;
    int w    = tid >> 5;
    int g    = lane >> 2;
    int t    = lane & 3;
    int bh   = blockIdx.y;
    int q0   = blockIdx.x * 128;
    size_t base = (size_t)bh * SS * HDIM;

    const float QS = NSCALE * LOG2E;

    int lrow = tid >> 2;          // 0..63
    int lcol = (tid & 3) * 16;    // 0,16,32,48

    unsigned kfrag = ks_base + (((lane & 7) * TSP + (lane >> 3) * 4) * 4);
    unsigned tfrag = ts_base + (((lane & 7) * TSP + (lane >> 3) * 4) * 4);
    float*   Pwp   = Ps + w * 16 * PSP;
    unsigned pfrag = ps_base + ((w * 16 * PSP +
                     (((lane >> 3) & 1) * 8 + (lane & 7)) * PSP + (lane >> 4) * 4) * 4);

    unsigned qa[8][4];
    {
        const float* Qp = Qin + base;
        int r0 = q0 + w * 16 + g;
        #pragma unroll
        for (int ks = 0; ks < 8; ks++) {
            qa[ks][0] = __float_as_uint(tf32r(Qp[(size_t)r0     * HDIM + ks*8 + t    ] * QS));
            qa[ks][1] = __float_as_uint(tf32r(Qp[(size_t)(r0+8) * HDIM + ks*8 + t    ] * QS));
            qa[ks][2] = __float_as_uint(tf32r(Qp[(size_t)r0     * HDIM + ks*8 + t + 4] * QS));
            qa[ks][3] = __float_as_uint(tf32r(Qp[(size_t)(r0+8) * HDIM + ks*8 + t + 4] * QS));
        }
    }

    float o[8][4];
    float l0, l1;
    constexpr int NT = SS / 64;   // 32

    auto flash_pass = [&](const float* __restrict__ Tsrc) {
        #pragma unroll
        for (int j = 0; j < 8; j++)
            #pragma unroll
            for (int q = 0; q < 4; q++) o[j][q] = 0.f;
        l0 = 0.f; l1 = 0.f;

        auto load_kv = [&](int kt, int stg) {
            const float* Kp = Kin  + base + (size_t)(kt*64 + lrow) * HDIM + lcol;
            const float* Tp = Tsrc + base + (size_t)lrow * SS + kt*64 + lcol;
            unsigned kd = ks_base + (stg * TILESZ + lrow * TSP + lcol) * 4;
            unsigned td = ts_base + (stg * TILESZ + lrow * TSP + lcol) * 4;
            #pragma unroll
            for (int i = 0; i < 4; i++) cpa16(kd + i*16, Kp + i*4);
            #pragma unroll
            for (int i = 0; i < 4; i++) cpa16(td + i*16, Tp + i*4);
        };

        load_kv(0, 0);
        cpa_commit();

        for (int kt = 0; kt < NT; kt++) {
            int cur = kt & 1;
            if (kt + 1 < NT) {
                load_kv(kt + 1, cur ^ 1);
                cpa_commit();
                cpa_wait1();
            } else {
                cpa_wait0();
            }
            __syncthreads();

            unsigned kf = kfrag + cur * TILESZ * 4;
            unsigned tf = tfrag + cur * TILESZ * 4;

            // S for one 8-key n-block (same accumulation order as before)
            auto compute_S = [&](int n, float* d) {
                d[0] = 0.f; d[1] = 0.f; d[2] = 0.f; d[3] = 0.f;
                #pragma unroll
                for (int cp = 0; cp < 4; cp++) {
                    unsigned b0, b1, b2, b3;
                    ldsm4(b0, b1, b2, b3, kf + (n*8*TSP + cp*16) * 4);
                    mma8(d, qa[2*cp    ], b0, b1);
                    mma8(d, qa[2*cp + 1], b2, b3);
                }
            };

            // key-group pipeline: sc = S of group i (n-blocks 2i, 2i+1)
            float sc[2][4], sn[2][4];
            compute_S(0, sc[0]);
            compute_S(1, sc[1]);

            #pragma unroll
            for (int i = 0; i < 4; i++) {
                // softmax of group i (p = 2^S), store P cols 16i..16i+15
                #pragma unroll
                for (int u = 0; u < 2; u++) {
                    int n = 2*i + u;
                    float p0 = ex2(sc[u][0]), p1 = ex2(sc[u][1]);
                    float p2 = ex2(sc[u][2]), p3 = ex2(sc[u][3]);
                    l0 += p0 + p1;
                    l1 += p2 + p3;
                    *(float2*)(Pwp +  g      * PSP + n*8 + 2*t) = make_float2(tf32r(p0), tf32r(p1));
                    *(float2*)(Pwp + (g + 8) * PSP + n*8 + 2*t) = make_float2(tf32r(p2), tf32r(p3));
                }
                // S of group i+1 in the MUFU/STS shadow (independent work)
                if (i < 3) {
                    compute_S(2*i + 2, sn[0]);
                    compute_S(2*i + 3, sn[1]);
                }
                __syncwarp();
                // P·V for group i (k-chunk i) — same order as cp-outer loop
                unsigned pa0[4], pa1[4];
                ldsm4(pa0[0], pa0[1], pa0[2], pa0[3], pfrag + (2*i    )*32);
                ldsm4(pa1[0], pa1[1], pa1[2], pa1[3], pfrag + (2*i + 1)*32);
                #pragma unroll
                for (int j = 0; j < 8; j++) {
                    unsigned v0, v1, v2, v3;
                    ldsm4(v0, v1, v2, v3, tf + (j*8*TSP + i*16) * 4);
                    mma8(o[j], pa0, v0, v1);
                    mma8(o[j], pa1, v2, v3);
                }
                if (i < 3) {
                    #pragma unroll
                    for (int u = 0; u < 2; u++)
                        #pragma unroll
                        for (int q = 0; q < 4; q++) sc[u][q] = sn[u][q];
                }
            }
            __syncthreads();
        }

        l0 += __shfl_xor_sync(0xffffffffu, l0, 1);
        l0 += __shfl_xor_sync(0xffffffffu, l0, 2);
        l1 += __shfl_xor_sync(0xffffffffu, l1, 1);
        l1 += __shfl_xor_sync(0xffffffffu, l1, 2);
    };

    // PASS 1: Hopfield update (V = K)
    flash_pass(Ktin);

    // Q2 = O/l rescaled by QS; round, store to P region, reload as a-frags.
    {
        float s0 = QS / l0, s1 = QS / l1;
        #pragma unroll
        for (int j = 0; j < 8; j++) {
            *(float2*)(Pwp +  g      * PSP + j*8 + 2*t) =
                make_float2(tf32r(o[j][0] * s0), tf32r(o[j][1] * s0));
            *(float2*)(Pwp + (g + 8) * PSP + j*8 + 2*t) =
                make_float2(tf32r(o[j][2] * s1), tf32r(o[j][3] * s1));
        }
        __syncwarp();
        #pragma unroll
        for (int ks = 0; ks < 8; ks++)
            ldsm4(qa[ks][0], qa[ks][1], qa[ks][2], qa[ks][3], pfrag + ks*32);
    }
    __syncthreads();

    // PASS 2: retrieval (V = V)
    flash_pass(Vtin);

    float inv0 = 1.f / l0, inv1 = 1.f / l1;
    int r0 = q0 + w * 16 + g;
    float* Op = Out + base;
    #pragma unroll
    for (int j = 0; j < 8; j++) {
        *(float2*)&Op[(size_t)r0     * HDIM + j*8 + 2*t] =
            make_float2(tf32r(o[j][0] * inv0), tf32r(o[j][1] * inv0));
        *(float2*)&Op[(size_t)(r0+8) * HDIM + j*8 + 2*t] =
            make_float2(tf32r(o[j][2] * inv1), tf32r(o[j][3] * inv1));
    }
}

// ---------------------------------------------------------------------------
// Launch
// ---------------------------------------------------------------------------
extern "C" void kernel_launch(void* const* d_in, const int* in_sizes, int n_in,
                              void* d_out, int out_size)
{
    const float* data = (const float*)d_in[0];
    const float* gk   = (const float*)d_in[1];
    const float* bk   = (const float*)d_in[2];
    const float* gq   = (const float*)d_in[3];
    const float* bq   = (const float*)d_in[4];
    const float* gv   = (const float*)d_in[5];
    const float* bv   = (const float*)d_in[6];
    const float* Wq   = (const float*)d_in[7];
    const float* bq2  = (const float*)d_in[8];
    const float* Wk   = (const float*)d_in[9];
    const float* bk2  = (const float*)d_in[10];
    const float* Wv   = (const float*)d_in[11];
    const float* bv2  = (const float*)d_in[12];
    const float* Wo   = (const float*)d_in[13];
    const float* bo   = (const float*)d_in[14];
    float* out = (float*)d_out;

    float *xq, *xk, *xv, *Q, *K, *V, *Kt, *Vt, *O, *rWq, *rWk, *rWv, *rWo;
    cudaGetSymbolAddress((void**)&xq, g_xq);
    cudaGetSymbolAddress((void**)&xk, g_xk);
    cudaGetSymbolAddress((void**)&xv, g_xv);
    cudaGetSymbolAddress((void**)&Q,  g_Q);
    cudaGetSymbolAddress((void**)&K,  g_K);
    cudaGetSymbolAddress((void**)&V,  g_V);
    cudaGetSymbolAddress((void**)&Kt, g_Kt);
    cudaGetSymbolAddress((void**)&Vt, g_Vt);
    cudaGetSymbolAddress((void**)&O,  g_O);
    cudaGetSymbolAddress((void**)&rWq, g_Wq);
    cudaGetSymbolAddress((void**)&rWk, g_Wk);
    cudaGetSymbolAddress((void**)&rWv, g_Wv);
    cudaGetSymbolAddress((void**)&rWo, g_Wo);

    static int attr_done = 0;
    if (!attr_done) {
        cudaFuncSetAttribute(attn_fused, cudaFuncAttributeMaxDynamicSharedMemorySize, ATTN_SMEM);
        attr_done = 1;
    }

    dim3 rwgrid(DD / 32, DD / 32, 4);
    dim3 rwblk(32, 8);
    roundw_t<<<rwgrid, rwblk>>>(Wq, Wk, Wv, Wo, rWq, rWk, rWv, rWo);

    ln3_kernel<<<TOK, 256>>>(data, gk, bk, gq, bq, gv, bv, xq, xk, xv);

    dim3 qkvgrid(DD / 128, TOK / 128, 3);       // (8, 32, 3)
    gemm_qkv<<<qkvgrid, 256>>>(xq, xk, xv, rWq, rWk, rWv, bq2, bk2, bv2, Q, K, V);

    dim3 tgrid(SS / 32, HDIM / 32, 2 * BB * HH);
    dim3 tblk(32, 8);
    transpose_both<<<tgrid, tblk>>>(K, Kt, V, Vt);

    dim3 agrid(SS / 128, BB * HH);              // (16, 32)
    attn_fused<<<agrid, 256, ATTN_SMEM>>>(Q, K, Kt, Vt, O);

    dim3 ogrid(DD / 128, TOK / 128);
    gemm_out<<<ogrid, 256>>>(O, rWo, bo, out);
}

// round 12
// speedup vs baseline: 2.2489x; 2.1329x over previous
#include <cuda_runtime.h>
#include <cuda_fp16.h>
#include <math.h>

// Problem constants
#define BB   2
#define SS   2048
#define DD   1024
#define HH   16
#define HDIM 64
#define TOK  (BB*SS)           // 4096 rows
#define NSCALE 0.125f          // 1/sqrt(64)
#define LOG2E  1.4426950408889634f
#define QSF   (NSCALE * LOG2E)

// ---------------------------------------------------------------------------
// Scratch (static __device__ arrays; no allocation allowed)
// ---------------------------------------------------------------------------
__device__ __half g_xq[TOK*DD];
__device__ __half g_xk[TOK*DD];
__device__ __half g_xv[TOK*DD];
__device__ __half g_Q [TOK*DD];   // head layout [B,H,S,HD], PRE-SCALED by QSF
__device__ __half g_K [TOK*DD];   // head layout
__device__ __half g_V [TOK*DD];
__device__ __half g_Kt[TOK*DD];   // transposed [B,H,HD,S]
__device__ __half g_Vt[TOK*DD];
__device__ __half g_O [TOK*DD];   // attention output, head layout
__device__ __half g_Wq[DD*DD];    // fp16, TRANSPOSED [n][k]
__device__ __half g_Wk[DD*DD];
__device__ __half g_Wv[DD*DD];
__device__ __half g_Wo[DD*DD];

// ---------------------------------------------------------------------------
// helpers
// ---------------------------------------------------------------------------
__device__ __forceinline__ float ex2(float x) {
    float y;
    asm("ex2.approx.ftz.f32 %0, %1;" : "=f"(y) : "f"(x));
    return y;
}
__device__ __forceinline__ void mma16(float* d, const unsigned* a, unsigned b0, unsigned b1) {
    asm volatile(
        "mma.sync.aligned.m16n8k16.row.col.f32.f16.f16.f32 "
        "{%0,%1,%2,%3}, {%4,%5,%6,%7}, {%8,%9}, {%0,%1,%2,%3};"
        : "+f"(d[0]), "+f"(d[1]), "+f"(d[2]), "+f"(d[3])
        : "r"(a[0]), "r"(a[1]), "r"(a[2]), "r"(a[3]), "r"(b0), "r"(b1));
}
__device__ __forceinline__ void ldsm4(unsigned& r0, unsigned& r1, unsigned& r2, unsigned& r3,
                                      unsigned addr) {
    asm volatile("ldmatrix.sync.aligned.m8n8.x4.shared.b16 {%0,%1,%2,%3}, [%4];"
        : "=r"(r0), "=r"(r1), "=r"(r2), "=r"(r3) : "r"(addr));
}
__device__ __forceinline__ void ldsm2(unsigned& r0, unsigned& r1, unsigned addr) {
    asm volatile("ldmatrix.sync.aligned.m8n8.x2.shared.b16 {%0,%1}, [%2];"
        : "=r"(r0), "=r"(r1) : "r"(addr));
}
__device__ __forceinline__ void cpa16(unsigned dst, const void* src) {
    asm volatile("cp.async.cg.shared.global [%0], [%1], 16;" :: "r"(dst), "l"(src));
}
__device__ __forceinline__ void cpa_commit() { asm volatile("cp.async.commit_group;"); }
__device__ __forceinline__ void cpa_wait0()  { asm volatile("cp.async.wait_group 0;"); }
__device__ __forceinline__ void cpa_wait1()  { asm volatile("cp.async.wait_group 1;"); }

// ---------------------------------------------------------------------------
// Weight convert + transpose: dst[n][k] = fp16(src[k][n])
// grid (DD/32, DD/32, 4), block (32, 8)
// ---------------------------------------------------------------------------
__global__ __launch_bounds__(256) void roundw_t(
    const float* __restrict__ w0, const float* __restrict__ w1,
    const float* __restrict__ w2, const float* __restrict__ w3,
    __half* __restrict__ d0, __half* __restrict__ d1,
    __half* __restrict__ d2, __half* __restrict__ d3)
{
    __shared__ float tile[32][33];
    const float* src; __half* dst;
    switch (blockIdx.z) {
        case 0: src = w0; dst = d0; break;
        case 1: src = w1; dst = d1; break;
        case 2: src = w2; dst = d2; break;
        default: src = w3; dst = d3; break;
    }
    int k0 = blockIdx.x * 32, n0 = blockIdx.y * 32;
    int x = threadIdx.x;
    #pragma unroll
    for (int r = threadIdx.y; r < 32; r += 8)
        tile[r][x] = src[(size_t)(k0 + r) * DD + n0 + x];
    __syncthreads();
    #pragma unroll
    for (int r = threadIdx.y; r < 32; r += 8)
        dst[(size_t)(n0 + r) * DD + k0 + x] = __float2half_rn(tile[x][r]);
}

// ---------------------------------------------------------------------------
// Per-head transpose (fp16): [B,H,S,HD] -> [B,H,HD,S]; K and V in one launch.
// grid (SS/32, HDIM/32, 2*BB*HH), block (32, 8)
// ---------------------------------------------------------------------------
__global__ __launch_bounds__(256) void transpose_both(
    const __half* __restrict__ srcA, __half* __restrict__ dstA,
    const __half* __restrict__ srcB, __half* __restrict__ dstB)
{
    __shared__ __half tile[32][34];
    int z  = blockIdx.z;
    int bh = z & (BB*HH - 1);
    const __half* src = (z < BB*HH) ? srcA : srcB;
    __half*       dst = (z < BB*HH) ? dstA : dstB;
    int s0 = blockIdx.x * 32, h0 = blockIdx.y * 32;
    const __half* S_ = src + (size_t)bh * SS * HDIM;
    __half* D_ = dst + (size_t)bh * SS * HDIM;
    int x = threadIdx.x;
    #pragma unroll
    for (int r = threadIdx.y; r < 32; r += 8)
        tile[r][x] = S_[(size_t)(s0 + r) * HDIM + h0 + x];
    __syncthreads();
    #pragma unroll
    for (int r = threadIdx.y; r < 32; r += 8)
        D_[(size_t)(h0 + r) * SS + s0 + x] = tile[x][r];
}

// ---------------------------------------------------------------------------
// Block reduction (256 threads)
// ---------------------------------------------------------------------------
__device__ __forceinline__ float blk_sum256(float v) {
    __shared__ float red[8];
    int lane = threadIdx.x & 31;
    int w    = threadIdx.x >> 5;
    #pragma unroll
    for (int o = 16; o > 0; o >>= 1) v += __shfl_xor_sync(0xffffffffu, v, o);
    __syncthreads();
    if (lane == 0) red[w] = v;
    __syncthreads();
    return red[0]+red[1]+red[2]+red[3]+red[4]+red[5]+red[6]+red[7];
}

// ---------------------------------------------------------------------------
// Fused triple LayerNorm (fp16 outputs)
// ---------------------------------------------------------------------------
__global__ __launch_bounds__(256) void ln3_kernel(
    const float* __restrict__ data,
    const float* __restrict__ gk, const float* __restrict__ bk,
    const float* __restrict__ gq, const float* __restrict__ bq,
    const float* __restrict__ gv, const float* __restrict__ bv,
    __half* __restrict__ xq, __half* __restrict__ xk, __half* __restrict__ xv)
{
    int row = blockIdx.x;
    int t   = threadIdx.x;
    const float4 x4 = ((const float4*)(data + (size_t)row * DD))[t];
    float s = x4.x + x4.y + x4.z + x4.w;
    float mean = blk_sum256(s) * (1.0f / DD);
    float d0 = x4.x - mean, d1 = x4.y - mean, d2 = x4.z - mean, d3 = x4.w - mean;
    float sq = d0*d0 + d1*d1 + d2*d2 + d3*d3;
    float var = blk_sum256(sq) * (1.0f / DD);
    float r = rsqrtf(var + 1e-5f);
    float n0 = d0*r, n1 = d1*r, n2 = d2*r, n3 = d3*r;

    float4 g4, b4;
    size_t base = (size_t)row * DD + t * 4;

    g4 = ((const float4*)gq)[t]; b4 = ((const float4*)bq)[t];
    *(__half2*)&xq[base]     = __floats2half2_rn(n0*g4.x + b4.x, n1*g4.y + b4.y);
    *(__half2*)&xq[base + 2] = __floats2half2_rn(n2*g4.z + b4.z, n3*g4.w + b4.w);

    g4 = ((const float4*)gk)[t]; b4 = ((const float4*)bk)[t];
    *(__half2*)&xk[base]     = __floats2half2_rn(n0*g4.x + b4.x, n1*g4.y + b4.y);
    *(__half2*)&xk[base + 2] = __floats2half2_rn(n2*g4.z + b4.z, n3*g4.w + b4.w);

    g4 = ((const float4*)gv)[t]; b4 = ((const float4*)bv)[t];
    *(__half2*)&xv[base]     = __floats2half2_rn(n0*g4.x + b4.x, n1*g4.y + b4.y);
    *(__half2*)&xv[base + 2] = __floats2half2_rn(n2*g4.z + b4.z, n3*g4.w + b4.w);
}

// ---------------------------------------------------------------------------
// fp16 GEMM body (mma.m16n8k16 + ldmatrix b16), cp.async 2-stage, BK=64.
// A [M,K] fp16 (or head-layout gather), W TRANSPOSED [N,K] fp16.
// OUT: 0 = fp32 row-major (Cf) | 1 = fp16 head layout (Ch), scaled by qscale
// ---------------------------------------------------------------------------
template<int MODE_IN, int OUT>
__device__ __forceinline__ void gemm_body(
    const __half* __restrict__ A, const __half* __restrict__ Wt,
    const float* __restrict__ bias, float* __restrict__ Cf,
    __half* __restrict__ Ch, float qscale)
{
    constexpr int BM = 128, BK = 64;
    constexpr int PH = 72;              // row pitch in halves (144B, conflict-free)
    constexpr int TSZ = BM * PH;        // halves per stage
    __shared__ __half As[2 * TSZ];
    __shared__ __half Bs[2 * TSZ];

    int tid  = threadIdx.x;
    int lane = tid & 31;
    int w    = tid >> 5;
    int g    = lane >> 2;
    int t    = lane & 3;
    int wm   = (w >> 2) * 64;
    int wn   = (w & 3) * 32;
    int bm   = blockIdx.y * BM;
    int bn   = blockIdx.x * BM;

    int lr = tid >> 1;                  // 0..127
    int lc = (tid & 1) * 32;            // halves: 0 or 32

    unsigned as_base = (unsigned)__cvta_generic_to_shared(As);
    unsigned bs_base = (unsigned)__cvta_generic_to_shared(Bs);

    // fragment base addresses (bytes)
    unsigned a_ld = as_base + (((lane & 15) * PH + (lane >> 4) * 8) * 2);
    unsigned b_ld = bs_base + (((lane & 7)  * PH + (lane >> 3) * 8) * 2);

    float acc[4][4][4];
    #pragma unroll
    for (int i = 0; i < 4; i++)
        #pragma unroll
        for (int j = 0; j < 4; j++)
            #pragma unroll
            for (int q = 0; q < 4; q++) acc[i][j][q] = 0.f;

    auto load_tile = [&](int it, int stg) {
        int kk = it * BK;
        int gm = bm + lr;
        int gk = kk + lc;
        const __half* pa;
        if (MODE_IN == 0) {
            pa = &A[(size_t)gm * DD + gk];
        } else {
            int b  = gm >> 11, s2 = gm & (SS - 1);
            int h  = gk >> 6,  hd = gk & (HDIM - 1);
            pa = &A[(((size_t)(b*HH + h) * SS + s2) * HDIM) + hd];
        }
        unsigned da = as_base + (stg * TSZ + lr * PH + lc) * 2;
        #pragma unroll
        for (int i = 0; i < 4; i++) cpa16(da + i*16, pa + i*8);
        const __half* pb = &Wt[(size_t)(bn + lr) * DD + kk + lc];
        unsigned db = bs_base + (stg * TSZ + lr * PH + lc) * 2;
        #pragma unroll
        for (int i = 0; i < 4; i++) cpa16(db + i*16, pb + i*8);
    };

    constexpr int KITER = DD / BK;      // 16
    load_tile(0, 0);
    cpa_commit();

    for (int it = 0; it < KITER; it++) {
        int cur = it & 1;
        if (it + 1 < KITER) {
            load_tile(it + 1, cur ^ 1);
            cpa_commit();
            cpa_wait1();
        } else {
            cpa_wait0();
        }
        __syncthreads();

        unsigned ab = a_ld + cur * TSZ * 2;
        unsigned bb = b_ld + cur * TSZ * 2;

        #pragma unroll
        for (int kh = 0; kh < 2; kh++) {         // 32-half chunks -> 2 ksteps each
            unsigned bf[4][4];
            #pragma unroll
            for (int ni = 0; ni < 4; ni++)
                ldsm4(bf[ni][0], bf[ni][1], bf[ni][2], bf[ni][3],
                      bb + ((wn + ni*8) * PH + kh*32) * 2);
            #pragma unroll
            for (int kp = 0; kp < 2; kp++) {
                unsigned af[4][4];
                #pragma unroll
                for (int mi = 0; mi < 4; mi++)
                    ldsm4(af[mi][0], af[mi][1], af[mi][2], af[mi][3],
                          ab + ((wm + mi*16) * PH + kh*32 + kp*16) * 2);
                #pragma unroll
                for (int mi = 0; mi < 4; mi++)
                    #pragma unroll
                    for (int ni = 0; ni < 4; ni++)
                        mma16(acc[mi][ni], af[mi], bf[ni][2*kp], bf[ni][2*kp + 1]);
            }
        }
        __syncthreads();
    }

    #pragma unroll
    for (int mi = 0; mi < 4; mi++) {
        #pragma unroll
        for (int ni = 0; ni < 4; ni++) {
            int row = bm + wm + mi * 16 + g;
            int col = bn + wn + ni * 8 + 2 * t;
            float2 bia = *(const float2*)&bias[col];
            float v00 = acc[mi][ni][0] + bia.x, v01 = acc[mi][ni][1] + bia.y;
            float v10 = acc[mi][ni][2] + bia.x, v11 = acc[mi][ni][3] + bia.y;
            if (OUT == 0) {
                *(float2*)&Cf[(size_t)row * DD + col]       = make_float2(v00, v01);
                *(float2*)&Cf[(size_t)(row + 8) * DD + col] = make_float2(v10, v11);
            } else {
                v00 *= qscale; v01 *= qscale; v10 *= qscale; v11 *= qscale;
                int h = col >> 6, hd = col & (HDIM - 1);
                int b0i = row >> 11,       s0 = row & (SS - 1);
                int b1i = (row + 8) >> 11, s1 = (row + 8) & (SS - 1);
                *(__half2*)&Ch[((size_t)(b0i*HH + h) * SS + s0) * HDIM + hd] =
                    __floats2half2_rn(v00, v01);
                *(__half2*)&Ch[((size_t)(b1i*HH + h) * SS + s1) * HDIM + hd] =
                    __floats2half2_rn(v10, v11);
            }
        }
    }
}

// Batched Q/K/V projection: grid (8, 32, 3). Q output pre-scaled by QSF.
__global__ __launch_bounds__(256, 2) void gemm_qkv(
    const __half* __restrict__ xq, const __half* __restrict__ xk, const __half* __restrict__ xv,
    const __half* __restrict__ Wq, const __half* __restrict__ Wk, const __half* __restrict__ Wv,
    const float* __restrict__ bq, const float* __restrict__ bk, const float* __restrict__ bv,
    __half* __restrict__ Q, __half* __restrict__ K, __half* __restrict__ V)
{
    if (blockIdx.z == 0)      gemm_body<0, 1>(xq, Wq, bq, nullptr, Q, QSF);
    else if (blockIdx.z == 1) gemm_body<0, 1>(xk, Wk, bk, nullptr, K, 1.0f);
    else                      gemm_body<0, 1>(xv, Wv, bv, nullptr, V, 1.0f);
}

// Output projection: grid (8, 32), fp32 out
__global__ __launch_bounds__(256, 2) void gemm_out(
    const __half* __restrict__ A, const __half* __restrict__ Wt,
    const float* __restrict__ bias, float* __restrict__ C)
{
    gemm_body<1, 0>(A, Wt, bias, C, nullptr, 1.0f);
}

// ---------------------------------------------------------------------------
// FUSED double-pass flash attention, fp16 mma.m16n8k16, key-group pipelined.
//   pass 1: Q2 = softmax(b Q K^T) K      (V^T source = Kt)
//   pass 2: O  = softmax(b Q2 K^T) V     (V^T source = Vt)
// Q is PRE-SCALED by QSF (beta*log2e); softmax = 2^s / sum.
// 256 threads = 8 warps; CTA = 128 queries (16/warp); K-tile 64 keys.
// Smem (halves): K[2][64*72] | T[2][64*72] | P[8][16*72]  (~55 KB)
// ---------------------------------------------------------------------------
#define APH 72
#define KTILE (64*APH)
#define PTILE (16*APH)
#define ATTN_SMEM ((4*KTILE + 8*PTILE) * 2)

__global__ __launch_bounds__(256, 2) void attn_fused(
    const __half* __restrict__ Qin, const __half* __restrict__ Kin,
    const __half* __restrict__ Ktin, const __half* __restrict__ Vtin,
    __half* __restrict__ Out)
{
    extern __shared__ __half smh[];
    __half* Ks = smh;                   // [2][KTILE]
    __half* Ts = smh + 2 * KTILE;       // [2][KTILE]
    __half* Ps = smh + 4 * KTILE;       // [8][PTILE]
    unsigned ks_base = (unsigned)__cvta_generic_to_shared(Ks);
    unsigned ts_base = (unsigned)__cvta_generic_to_shared(Ts);
    unsigned ps_base = (unsigned)__cvta_generic_to_shared(Ps);

    int tid  = threadIdx.x;
    int lane = tid & 31;
    int w    = tid >> 5;
    int g    = lane >> 2;
    int t    = lane & 3;
    int bh   = blockIdx.y;
    int q0   = blockIdx.x * 128;
    size_t base = (size_t)bh * SS * HDIM;

    int lrow = tid >> 2;                // 0..63
    int lch  = (tid & 3) * 16;          // halves: 0,16,32,48

    // fragment base addresses (bytes)
    unsigned kfB  = ks_base + (((lane & 7) * APH + (lane >> 3) * 8) * 2);        // B x4
    unsigned tfB2 = ts_base + (((lane & 7) * APH + ((lane >> 3) & 1) * 8) * 2);  // B x2
    __half*  Pwp  = Ps + w * PTILE;
    unsigned pfA  = ps_base + ((w * PTILE + (lane & 15) * APH + (lane >> 4) * 8) * 2);

    // Q fragments (already x QSF in global)
    unsigned qa[4][4];
    {
        const __half* Qp = Qin + base;
        int r0 = q0 + w * 16 + g;
        #pragma unroll
        for (int s = 0; s < 4; s++) {
            qa[s][0] = *(const unsigned*)&Qp[(size_t)r0     * HDIM + s*16 + 2*t    ];
            qa[s][1] = *(const unsigned*)&Qp[(size_t)(r0+8) * HDIM + s*16 + 2*t    ];
            qa[s][2] = *(const unsigned*)&Qp[(size_t)r0     * HDIM + s*16 + 2*t + 8];
            qa[s][3] = *(const unsigned*)&Qp[(size_t)(r0+8) * HDIM + s*16 + 2*t + 8];
        }
    }

    float o[8][4];
    float l0, l1;
    constexpr int NT = SS / 64;         // 32

    auto flash_pass = [&](const __half* __restrict__ Tsrc) {
        #pragma unroll
        for (int j = 0; j < 8; j++)
            #pragma unroll
            for (int q = 0; q < 4; q++) o[j][q] = 0.f;
        l0 = 0.f; l1 = 0.f;

        auto load_kv = [&](int kt, int stg) {
            const __half* Kp = Kin  + base + (size_t)(kt*64 + lrow) * HDIM + lch;
            const __half* Tp = Tsrc + base + (size_t)lrow * SS + kt*64 + lch;
            unsigned kd = ks_base + (stg * KTILE + lrow * APH + lch) * 2;
            unsigned td = ts_base + (stg * KTILE + lrow * APH + lch) * 2;
            cpa16(kd,      Kp);
            cpa16(kd + 16, Kp + 8);
            cpa16(td,      Tp);
            cpa16(td + 16, Tp + 8);
        };

        load_kv(0, 0);
        cpa_commit();

        for (int kt = 0; kt < NT; kt++) {
            int cur = kt & 1;
            if (kt + 1 < NT) {
                load_kv(kt + 1, cur ^ 1);
                cpa_commit();
                cpa_wait1();
            } else {
                cpa_wait0();
            }
            __syncthreads();

            unsigned kf = kfB  + cur * KTILE * 2;
            unsigned tf = tfB2 + cur * KTILE * 2;

            // S for one 8-key n-block (hd = 64 -> 4 ksteps)
            auto compute_S = [&](int n, float* d) {
                d[0] = 0.f; d[1] = 0.f; d[2] = 0.f; d[3] = 0.f;
                unsigned b0, b1, b2, b3;
                ldsm4(b0, b1, b2, b3, kf + (n*8*APH) * 2);
                mma16(d, qa[0], b0, b1);
                mma16(d, qa[1], b2, b3);
                ldsm4(b0, b1, b2, b3, kf + (n*8*APH + 32) * 2);
                mma16(d, qa[2], b0, b1);
                mma16(d, qa[3], b2, b3);
            };

            float sc[2][4], sn[2][4];
            compute_S(0, sc[0]);
            compute_S(1, sc[1]);

            #pragma unroll
            for (int i = 0; i < 4; i++) {
                // softmax of group i (16 keys), store P as fp16
                #pragma unroll
                for (int u = 0; u < 2; u++) {
                    int n = 2*i + u;
                    float p0 = ex2(sc[u][0]), p1 = ex2(sc[u][1]);
                    float p2 = ex2(sc[u][2]), p3 = ex2(sc[u][3]);
                    l0 += p0 + p1;
                    l1 += p2 + p3;
                    *(__half2*)(Pwp +  g      * APH + n*8 + 2*t) = __floats2half2_rn(p0, p1);
                    *(__half2*)(Pwp + (g + 8) * APH + n*8 + 2*t) = __floats2half2_rn(p2, p3);
                }
                // S of group i+1 in the MUFU/STS shadow
                if (i < 3) {
                    compute_S(2*i + 2, sn[0]);
                    compute_S(2*i + 3, sn[1]);
                }
                __syncwarp();
                // O += P V for group i (kstep i)
                unsigned pa[4];
                ldsm4(pa[0], pa[1], pa[2], pa[3], pfA + i*32);
                #pragma unroll
                for (int j = 0; j < 8; j++) {
                    unsigned v0, v1;
                    ldsm2(v0, v1, tf + (j*8*APH + i*16) * 2);
                    mma16(o[j], pa, v0, v1);
                }
                if (i < 3) {
                    #pragma unroll
                    for (int u = 0; u < 2; u++)
                        #pragma unroll
                        for (int q = 0; q < 4; q++) sc[u][q] = sn[u][q];
                }
            }
            __syncthreads();
        }

        l0 += __shfl_xor_sync(0xffffffffu, l0, 1);
        l0 += __shfl_xor_sync(0xffffffffu, l0, 2);
        l1 += __shfl_xor_sync(0xffffffffu, l1, 1);
        l1 += __shfl_xor_sync(0xffffffffu, l1, 2);
    };

    // PASS 1: Hopfield update (V = K)
    flash_pass(Ktin);

    // Q2 = (O / l) * QSF; store fp16 to P region, reload as A-frags.
    {
        float s0 = QSF / l0, s1 = QSF / l1;
        #pragma unroll
        for (int j = 0; j < 8; j++) {
            *(__half2*)(Pwp +  g      * APH + j*8 + 2*t) =
                __floats2half2_rn(o[j][0] * s0, o[j][1] * s0);
            *(__half2*)(Pwp + (g + 8) * APH + j*8 + 2*t) =
                __floats2half2_rn(o[j][2] * s1, o[j][3] * s1);
        }
        __syncwarp();
        #pragma unroll
        for (int s = 0; s < 4; s++)
            ldsm4(qa[s][0], qa[s][1], qa[s][2], qa[s][3], pfA + s*32);
    }
    __syncthreads();

    // PASS 2: retrieval (V = V)
    flash_pass(Vtin);

    // epilogue: O / l -> fp16 (consumed by gemm_out)
    float inv0 = 1.f / l0, inv1 = 1.f / l1;
    int r0 = q0 + w * 16 + g;
    __half* Op = Out + base;
    #pragma unroll
    for (int j = 0; j < 8; j++) {
        *(__half2*)&Op[(size_t)r0     * HDIM + j*8 + 2*t] =
            __floats2half2_rn(o[j][0] * inv0, o[j][1] * inv0);
        *(__half2*)&Op[(size_t)(r0+8) * HDIM + j*8 + 2*t] =
            __floats2half2_rn(o[j][2] * inv1, o[j][3] * inv1);
    }
}

// ---------------------------------------------------------------------------
// Launch
// ---------------------------------------------------------------------------
extern "C" void kernel_launch(void* const* d_in, const int* in_sizes, int n_in,
                              void* d_out, int out_size)
{
    const float* data = (const float*)d_in[0];
    const float* gk   = (const float*)d_in[1];
    const float* bk   = (const float*)d_in[2];
    const float* gq   = (const float*)d_in[3];
    const float* bq   = (const float*)d_in[4];
    const float* gv   = (const float*)d_in[5];
    const float* bv   = (const float*)d_in[6];
    const float* Wq   = (const float*)d_in[7];
    const float* bq2  = (const float*)d_in[8];
    const float* Wk   = (const float*)d_in[9];
    const float* bk2  = (const float*)d_in[10];
    const float* Wv   = (const float*)d_in[11];
    const float* bv2  = (const float*)d_in[12];
    const float* Wo   = (const float*)d_in[13];
    const float* bo   = (const float*)d_in[14];
    float* out = (float*)d_out;

    __half *xq, *xk, *xv, *Q, *K, *V, *Kt, *Vt, *O, *rWq, *rWk, *rWv, *rWo;
    cudaGetSymbolAddress((void**)&xq, g_xq);
    cudaGetSymbolAddress((void**)&xk, g_xk);
    cudaGetSymbolAddress((void**)&xv, g_xv);
    cudaGetSymbolAddress((void**)&Q,  g_Q);
    cudaGetSymbolAddress((void**)&K,  g_K);
    cudaGetSymbolAddress((void**)&V,  g_V);
    cudaGetSymbolAddress((void**)&Kt, g_Kt);
    cudaGetSymbolAddress((void**)&Vt, g_Vt);
    cudaGetSymbolAddress((void**)&O,  g_O);
    cudaGetSymbolAddress((void**)&rWq, g_Wq);
    cudaGetSymbolAddress((void**)&rWk, g_Wk);
    cudaGetSymbolAddress((void**)&rWv, g_Wv);
    cudaGetSymbolAddress((void**)&rWo, g_Wo);

    static int attr_done = 0;
    if (!attr_done) {
        cudaFuncSetAttribute(attn_fused, cudaFuncAttributeMaxDynamicSharedMemorySize, ATTN_SMEM);
        attr_done = 1;
    }

    dim3 rwgrid(DD / 32, DD / 32, 4);
    dim3 rwblk(32, 8);
    roundw_t<<<rwgrid, rwblk>>>(Wq, Wk, Wv, Wo, rWq, rWk, rWv, rWo);

    ln3_kernel<<<TOK, 256>>>(data, gk, bk, gq, bq, gv, bv, xq, xk, xv);

    dim3 qkvgrid(DD / 128, TOK / 128, 3);       // (8, 32, 3)
    gemm_qkv<<<qkvgrid, 256>>>(xq, xk, xv, rWq, rWk, rWv, bq2, bk2, bv2, Q, K, V);

    dim3 tgrid(SS / 32, HDIM / 32, 2 * BB * HH);
    dim3 tblk(32, 8);
    transpose_both<<<tgrid, tblk>>>(K, Kt, V, Vt);

    dim3 agrid(SS / 128, BB * HH);              // (16, 32)
    attn_fused<<<agrid, 256, ATTN_SMEM>>>(Q, K, Kt, Vt, O);

    dim3 ogrid(DD / 128, TOK / 128);
    gemm_out<<<ogrid, 256>>>(O, rWo, bo, out);
}

// round 13
// speedup vs baseline: 2.3603x; 1.0495x over previous
#include <cuda_runtime.h>
#include <cuda_fp16.h>
#include <math.h>

// Problem constants
#define BB   2
#define SS   2048
#define DD   1024
#define HH   16
#define HDIM 64
#define TOK  (BB*SS)           // 4096 rows
#define NSCALE 0.125f          // 1/sqrt(64)
#define LOG2E  1.4426950408889634f
#define QSF   (NSCALE * LOG2E)

// ---------------------------------------------------------------------------
// Scratch (static __device__ arrays; no allocation allowed)
// ---------------------------------------------------------------------------
__device__ __half g_xq[TOK*DD];
__device__ __half g_xk[TOK*DD];
__device__ __half g_xv[TOK*DD];
__device__ __half g_Q [TOK*DD];   // head layout [B,H,S,HD], PRE-SCALED by QSF
__device__ __half g_K [TOK*DD];   // head layout
__device__ __half g_V [TOK*DD];
__device__ __half g_O [TOK*DD];   // attention output, head layout
__device__ __half g_Wq[DD*DD];    // fp16, TRANSPOSED [n][k]
__device__ __half g_Wk[DD*DD];
__device__ __half g_Wv[DD*DD];
__device__ __half g_Wo[DD*DD];

// ---------------------------------------------------------------------------
// helpers
// ---------------------------------------------------------------------------
__device__ __forceinline__ float ex2(float x) {
    float y;
    asm("ex2.approx.ftz.f32 %0, %1;" : "=f"(y) : "f"(x));
    return y;
}
__device__ __forceinline__ void mma16(float* d, const unsigned* a, unsigned b0, unsigned b1) {
    asm volatile(
        "mma.sync.aligned.m16n8k16.row.col.f32.f16.f16.f32 "
        "{%0,%1,%2,%3}, {%4,%5,%6,%7}, {%8,%9}, {%0,%1,%2,%3};"
        : "+f"(d[0]), "+f"(d[1]), "+f"(d[2]), "+f"(d[3])
        : "r"(a[0]), "r"(a[1]), "r"(a[2]), "r"(a[3]), "r"(b0), "r"(b1));
}
__device__ __forceinline__ void ldsm4(unsigned& r0, unsigned& r1, unsigned& r2, unsigned& r3,
                                      unsigned addr) {
    asm volatile("ldmatrix.sync.aligned.m8n8.x4.shared.b16 {%0,%1,%2,%3}, [%4];"
        : "=r"(r0), "=r"(r1), "=r"(r2), "=r"(r3) : "r"(addr));
}
__device__ __forceinline__ void ldsm2t(unsigned& r0, unsigned& r1, unsigned addr) {
    asm volatile("ldmatrix.sync.aligned.m8n8.x2.trans.shared.b16 {%0,%1}, [%2];"
        : "=r"(r0), "=r"(r1) : "r"(addr));
}
__device__ __forceinline__ void cpa16(unsigned dst, const void* src) {
    asm volatile("cp.async.cg.shared.global [%0], [%1], 16;" :: "r"(dst), "l"(src));
}
__device__ __forceinline__ void cpa_commit() { asm volatile("cp.async.commit_group;"); }
__device__ __forceinline__ void cpa_wait0()  { asm volatile("cp.async.wait_group 0;"); }
__device__ __forceinline__ void cpa_wait1()  { asm volatile("cp.async.wait_group 1;"); }

// ---------------------------------------------------------------------------
// Weight convert + transpose: dst[n][k] = fp16(src[k][n])
// grid (DD/32, DD/32, 4), block (32, 8)
// ---------------------------------------------------------------------------
__global__ __launch_bounds__(256) void roundw_t(
    const float* __restrict__ w0, const float* __restrict__ w1,
    const float* __restrict__ w2, const float* __restrict__ w3,
    __half* __restrict__ d0, __half* __restrict__ d1,
    __half* __restrict__ d2, __half* __restrict__ d3)
{
    __shared__ float tile[32][33];
    const float* src; __half* dst;
    switch (blockIdx.z) {
        case 0: src = w0; dst = d0; break;
        case 1: src = w1; dst = d1; break;
        case 2: src = w2; dst = d2; break;
        default: src = w3; dst = d3; break;
    }
    int k0 = blockIdx.x * 32, n0 = blockIdx.y * 32;
    int x = threadIdx.x;
    #pragma unroll
    for (int r = threadIdx.y; r < 32; r += 8)
        tile[r][x] = src[(size_t)(k0 + r) * DD + n0 + x];
    __syncthreads();
    #pragma unroll
    for (int r = threadIdx.y; r < 32; r += 8)
        dst[(size_t)(n0 + r) * DD + k0 + x] = __float2half_rn(tile[x][r]);
}

// ---------------------------------------------------------------------------
// Block reduction (256 threads)
// ---------------------------------------------------------------------------
__device__ __forceinline__ float blk_sum256(float v) {
    __shared__ float red[8];
    int lane = threadIdx.x & 31;
    int w    = threadIdx.x >> 5;
    #pragma unroll
    for (int o = 16; o > 0; o >>= 1) v += __shfl_xor_sync(0xffffffffu, v, o);
    __syncthreads();
    if (lane == 0) red[w] = v;
    __syncthreads();
    return red[0]+red[1]+red[2]+red[3]+red[4]+red[5]+red[6]+red[7];
}

// ---------------------------------------------------------------------------
// Fused triple LayerNorm (fp16 outputs)
// ---------------------------------------------------------------------------
__global__ __launch_bounds__(256) void ln3_kernel(
    const float* __restrict__ data,
    const float* __restrict__ gk, const float* __restrict__ bk,
    const float* __restrict__ gq, const float* __restrict__ bq,
    const float* __restrict__ gv, const float* __restrict__ bv,
    __half* __restrict__ xq, __half* __restrict__ xk, __half* __restrict__ xv)
{
    int row = blockIdx.x;
    int t   = threadIdx.x;
    const float4 x4 = ((const float4*)(data + (size_t)row * DD))[t];
    float s = x4.x + x4.y + x4.z + x4.w;
    float mean = blk_sum256(s) * (1.0f / DD);
    float d0 = x4.x - mean, d1 = x4.y - mean, d2 = x4.z - mean, d3 = x4.w - mean;
    float sq = d0*d0 + d1*d1 + d2*d2 + d3*d3;
    float var = blk_sum256(sq) * (1.0f / DD);
    float r = rsqrtf(var + 1e-5f);
    float n0 = d0*r, n1 = d1*r, n2 = d2*r, n3 = d3*r;

    float4 g4, b4;
    size_t base = (size_t)row * DD + t * 4;

    g4 = ((const float4*)gq)[t]; b4 = ((const float4*)bq)[t];
    *(__half2*)&xq[base]     = __floats2half2_rn(n0*g4.x + b4.x, n1*g4.y + b4.y);
    *(__half2*)&xq[base + 2] = __floats2half2_rn(n2*g4.z + b4.z, n3*g4.w + b4.w);

    g4 = ((const float4*)gk)[t]; b4 = ((const float4*)bk)[t];
    *(__half2*)&xk[base]     = __floats2half2_rn(n0*g4.x + b4.x, n1*g4.y + b4.y);
    *(__half2*)&xk[base + 2] = __floats2half2_rn(n2*g4.z + b4.z, n3*g4.w + b4.w);

    g4 = ((const float4*)gv)[t]; b4 = ((const float4*)bv)[t];
    *(__half2*)&xv[base]     = __floats2half2_rn(n0*g4.x + b4.x, n1*g4.y + b4.y);
    *(__half2*)&xv[base + 2] = __floats2half2_rn(n2*g4.z + b4.z, n3*g4.w + b4.w);
}

// ---------------------------------------------------------------------------
// fp16 GEMM body (mma.m16n8k16 + ldmatrix b16), cp.async 2-stage, BK=64.
// A [M,K] fp16 (or head-layout gather), W TRANSPOSED [N,K] fp16.
// OUT: 0 = fp32 row-major (Cf) | 1 = fp16 head layout (Ch), scaled by qscale
// ---------------------------------------------------------------------------
template<int MODE_IN, int OUT>
__device__ __forceinline__ void gemm_body(
    const __half* __restrict__ A, const __half* __restrict__ Wt,
    const float* __restrict__ bias, float* __restrict__ Cf,
    __half* __restrict__ Ch, float qscale)
{
    constexpr int BM = 128, BK = 64;
    constexpr int PH = 72;              // row pitch in halves (144B, conflict-free)
    constexpr int TSZ = BM * PH;        // halves per stage
    __shared__ __half As[2 * TSZ];
    __shared__ __half Bs[2 * TSZ];

    int tid  = threadIdx.x;
    int lane = tid & 31;
    int w    = tid >> 5;
    int g    = lane >> 2;
    int t    = lane & 3;
    int wm   = (w >> 2) * 64;
    int wn   = (w & 3) * 32;
    int bm   = blockIdx.y * BM;
    int bn   = blockIdx.x * BM;

    int lr = tid >> 1;                  // 0..127
    int lc = (tid & 1) * 32;            // halves: 0 or 32

    unsigned as_base = (unsigned)__cvta_generic_to_shared(As);
    unsigned bs_base = (unsigned)__cvta_generic_to_shared(Bs);

    // fragment base addresses (bytes)
    unsigned a_ld = as_base + (((lane & 15) * PH + (lane >> 4) * 8) * 2);
    unsigned b_ld = bs_base + (((lane & 7)  * PH + (lane >> 3) * 8) * 2);

    float acc[4][4][4];
    #pragma unroll
    for (int i = 0; i < 4; i++)
        #pragma unroll
        for (int j = 0; j < 4; j++)
            #pragma unroll
            for (int q = 0; q < 4; q++) acc[i][j][q] = 0.f;

    auto load_tile = [&](int it, int stg) {
        int kk = it * BK;
        int gm = bm + lr;
        int gk = kk + lc;
        const __half* pa;
        if (MODE_IN == 0) {
            pa = &A[(size_t)gm * DD + gk];
        } else {
            int b  = gm >> 11, s2 = gm & (SS - 1);
            int h  = gk >> 6,  hd = gk & (HDIM - 1);
            pa = &A[(((size_t)(b*HH + h) * SS + s2) * HDIM) + hd];
        }
        unsigned da = as_base + (stg * TSZ + lr * PH + lc) * 2;
        #pragma unroll
        for (int i = 0; i < 4; i++) cpa16(da + i*16, pa + i*8);
        const __half* pb = &Wt[(size_t)(bn + lr) * DD + kk + lc];
        unsigned db = bs_base + (stg * TSZ + lr * PH + lc) * 2;
        #pragma unroll
        for (int i = 0; i < 4; i++) cpa16(db + i*16, pb + i*8);
    };

    constexpr int KITER = DD / BK;      // 16
    load_tile(0, 0);
    cpa_commit();

    for (int it = 0; it < KITER; it++) {
        int cur = it & 1;
        if (it + 1 < KITER) {
            load_tile(it + 1, cur ^ 1);
            cpa_commit();
            cpa_wait1();
        } else {
            cpa_wait0();
        }
        __syncthreads();

        unsigned ab = a_ld + cur * TSZ * 2;
        unsigned bb = b_ld + cur * TSZ * 2;

        #pragma unroll
        for (int kh = 0; kh < 2; kh++) {         // 32-half chunks -> 2 ksteps each
            unsigned bf[4][4];
            #pragma unroll
            for (int ni = 0; ni < 4; ni++)
                ldsm4(bf[ni][0], bf[ni][1], bf[ni][2], bf[ni][3],
                      bb + ((wn + ni*8) * PH + kh*32) * 2);
            #pragma unroll
            for (int kp = 0; kp < 2; kp++) {
                unsigned af[4][4];
                #pragma unroll
                for (int mi = 0; mi < 4; mi++)
                    ldsm4(af[mi][0], af[mi][1], af[mi][2], af[mi][3],
                          ab + ((wm + mi*16) * PH + kh*32 + kp*16) * 2);
                #pragma unroll
                for (int mi = 0; mi < 4; mi++)
                    #pragma unroll
                    for (int ni = 0; ni < 4; ni++)
                        mma16(acc[mi][ni], af[mi], bf[ni][2*kp], bf[ni][2*kp + 1]);
            }
        }
        __syncthreads();
    }

    #pragma unroll
    for (int mi = 0; mi < 4; mi++) {
        #pragma unroll
        for (int ni = 0; ni < 4; ni++) {
            int row = bm + wm + mi * 16 + g;
            int col = bn + wn + ni * 8 + 2 * t;
            float2 bia = *(const float2*)&bias[col];
            float v00 = acc[mi][ni][0] + bia.x, v01 = acc[mi][ni][1] + bia.y;
            float v10 = acc[mi][ni][2] + bia.x, v11 = acc[mi][ni][3] + bia.y;
            if (OUT == 0) {
                *(float2*)&Cf[(size_t)row * DD + col]       = make_float2(v00, v01);
                *(float2*)&Cf[(size_t)(row + 8) * DD + col] = make_float2(v10, v11);
            } else {
                v00 *= qscale; v01 *= qscale; v10 *= qscale; v11 *= qscale;
                int h = col >> 6, hd = col & (HDIM - 1);
                int b0i = row >> 11,       s0 = row & (SS - 1);
                int b1i = (row + 8) >> 11, s1 = (row + 8) & (SS - 1);
                *(__half2*)&Ch[((size_t)(b0i*HH + h) * SS + s0) * HDIM + hd] =
                    __floats2half2_rn(v00, v01);
                *(__half2*)&Ch[((size_t)(b1i*HH + h) * SS + s1) * HDIM + hd] =
                    __floats2half2_rn(v10, v11);
            }
        }
    }
}

// Batched Q/K/V projection: grid (8, 32, 3). Q output pre-scaled by QSF.
__global__ __launch_bounds__(256, 2) void gemm_qkv(
    const __half* __restrict__ xq, const __half* __restrict__ xk, const __half* __restrict__ xv,
    const __half* __restrict__ Wq, const __half* __restrict__ Wk, const __half* __restrict__ Wv,
    const float* __restrict__ bq, const float* __restrict__ bk, const float* __restrict__ bv,
    __half* __restrict__ Q, __half* __restrict__ K, __half* __restrict__ V)
{
    if (blockIdx.z == 0)      gemm_body<0, 1>(xq, Wq, bq, nullptr, Q, QSF);
    else if (blockIdx.z == 1) gemm_body<0, 1>(xk, Wk, bk, nullptr, K, 1.0f);
    else                      gemm_body<0, 1>(xv, Wv, bv, nullptr, V, 1.0f);
}

// Output projection: grid (8, 32), fp32 out
__global__ __launch_bounds__(256, 2) void gemm_out(
    const __half* __restrict__ A, const __half* __restrict__ Wt,
    const float* __restrict__ bias, float* __restrict__ C)
{
    gemm_body<1, 0>(A, Wt, bias, C, nullptr, 1.0f);
}

// ---------------------------------------------------------------------------
// FUSED double-pass flash attention, fp16 m16n8k16, ldmatrix.trans for P*V.
//   pass 1: Q2 = softmax(b Q K^T) K      (V tile := K tile, no extra load)
//   pass 2: O  = softmax(b Q2 K^T) V
// Q is PRE-SCALED by QSF (beta*log2e); softmax = 2^s / sum.
// 256 threads = 8 warps; CTA = 128 queries (16/warp); K-tile 64 keys.
// Smem (halves): K[2][64*72] | V[2][64*72] | P[8][16*72]  (~55 KB)
// ---------------------------------------------------------------------------
#define APH 72
#define KTILE (64*APH)
#define PTILE (16*APH)
#define ATTN_SMEM ((4*KTILE + 8*PTILE) * 2)

__global__ __launch_bounds__(256, 2) void attn_fused(
    const __half* __restrict__ Qin, const __half* __restrict__ Kin,
    const __half* __restrict__ Vin, __half* __restrict__ Out)
{
    extern __shared__ __half smh[];
    __half* Ks = smh;                   // [2][KTILE]  key x hd
    __half* Vs = smh + 2 * KTILE;       // [2][KTILE]  key x hd (natural layout)
    __half* Ps = smh + 4 * KTILE;       // [8][PTILE]
    unsigned ks_base = (unsigned)__cvta_generic_to_shared(Ks);
    unsigned vs_base = (unsigned)__cvta_generic_to_shared(Vs);
    unsigned ps_base = (unsigned)__cvta_generic_to_shared(Ps);

    int tid  = threadIdx.x;
    int lane = tid & 31;
    int w    = tid >> 5;
    int g    = lane >> 2;
    int t    = lane & 3;
    int bh   = blockIdx.y;
    int q0   = blockIdx.x * 128;
    size_t base = (size_t)bh * SS * HDIM;

    int lrow = tid >> 2;                // 0..63
    int lch  = (tid & 3) * 16;          // halves: 0,16,32,48

    // fragment per-lane offsets (bytes)
    unsigned kfB   = ks_base + (((lane & 7) * APH + (lane >> 3) * 8) * 2);   // K: B x4 non-trans
    unsigned vlane = ((lane & 15) * APH) * 2;                                 // V: B x2 trans
    __half*  Pwp   = Ps + w * PTILE;
    unsigned pfA   = ps_base + ((w * PTILE + (lane & 15) * APH + (lane >> 4) * 8) * 2);

    // Q fragments (already x QSF in global)
    unsigned qa[4][4];
    {
        const __half* Qp = Qin + base;
        int r0 = q0 + w * 16 + g;
        #pragma unroll
        for (int s = 0; s < 4; s++) {
            qa[s][0] = *(const unsigned*)&Qp[(size_t)r0     * HDIM + s*16 + 2*t    ];
            qa[s][1] = *(const unsigned*)&Qp[(size_t)(r0+8) * HDIM + s*16 + 2*t    ];
            qa[s][2] = *(const unsigned*)&Qp[(size_t)r0     * HDIM + s*16 + 2*t + 8];
            qa[s][3] = *(const unsigned*)&Qp[(size_t)(r0+8) * HDIM + s*16 + 2*t + 8];
        }
    }

    float o[8][4];
    float l0, l1;
    constexpr int NT = SS / 64;         // 32

    // PASS = 0: V tile aliases K tile (no V loads). PASS = 1: load V too.
    auto flash_pass = [&](const __half* __restrict__ Vsrc, int loadV) {
        #pragma unroll
        for (int j = 0; j < 8; j++)
            #pragma unroll
            for (int q = 0; q < 4; q++) o[j][q] = 0.f;
        l0 = 0.f; l1 = 0.f;

        unsigned vbase = loadV ? vs_base : ks_base;

        auto load_kv = [&](int kt, int stg) {
            const __half* Kp = Kin + base + (size_t)(kt*64 + lrow) * HDIM + lch;
            unsigned kd = ks_base + (stg * KTILE + lrow * APH + lch) * 2;
            cpa16(kd,      Kp);
            cpa16(kd + 16, Kp + 8);
            if (loadV) {
                const __half* Vp = Vsrc + base + (size_t)(kt*64 + lrow) * HDIM + lch;
                unsigned vd = vs_base + (stg * KTILE + lrow * APH + lch) * 2;
                cpa16(vd,      Vp);
                cpa16(vd + 16, Vp + 8);
            }
        };

        load_kv(0, 0);
        cpa_commit();

        for (int kt = 0; kt < NT; kt++) {
            int cur = kt & 1;
            if (kt + 1 < NT) {
                load_kv(kt + 1, cur ^ 1);
                cpa_commit();
                cpa_wait1();
            } else {
                cpa_wait0();
            }
            __syncthreads();

            unsigned kf = kfB + cur * KTILE * 2;
            unsigned vf = vbase + cur * KTILE * 2 + vlane;

            // S for one 8-key n-block (hd = 64 -> 4 ksteps)
            auto compute_S = [&](int n, float* d) {
                d[0] = 0.f; d[1] = 0.f; d[2] = 0.f; d[3] = 0.f;
                unsigned b0, b1, b2, b3;
                ldsm4(b0, b1, b2, b3, kf + (n*8*APH) * 2);
                mma16(d, qa[0], b0, b1);
                mma16(d, qa[1], b2, b3);
                ldsm4(b0, b1, b2, b3, kf + (n*8*APH + 32) * 2);
                mma16(d, qa[2], b0, b1);
                mma16(d, qa[3], b2, b3);
            };

            float sc[2][4], sn[2][4];
            compute_S(0, sc[0]);
            compute_S(1, sc[1]);

            #pragma unroll
            for (int i = 0; i < 4; i++) {
                // softmax of group i (16 keys), store P as fp16
                #pragma unroll
                for (int u = 0; u < 2; u++) {
                    int n = 2*i + u;
                    float p0 = ex2(sc[u][0]), p1 = ex2(sc[u][1]);
                    float p2 = ex2(sc[u][2]), p3 = ex2(sc[u][3]);
                    l0 += p0 + p1;
                    l1 += p2 + p3;
                    *(__half2*)(Pwp +  g      * APH + n*8 + 2*t) = __floats2half2_rn(p0, p1);
                    *(__half2*)(Pwp + (g + 8) * APH + n*8 + 2*t) = __floats2half2_rn(p2, p3);
                }
                // S of group i+1 in the MUFU/STS shadow
                if (i < 3) {
                    compute_S(2*i + 2, sn[0]);
                    compute_S(2*i + 3, sn[1]);
                }
                __syncwarp();
                // O += P V for group i: B-fragments via ldmatrix.trans from
                // the natural-layout V tile (rows = keys 16i..16i+15)
                unsigned pa[4];
                ldsm4(pa[0], pa[1], pa[2], pa[3], pfA + i*32);
                #pragma unroll
                for (int j = 0; j < 8; j++) {
                    unsigned v0, v1;
                    ldsm2t(v0, v1, vf + (i*16*APH + j*8) * 2);
                    mma16(o[j], pa, v0, v1);
                }
                if (i < 3) {
                    #pragma unroll
                    for (int u = 0; u < 2; u++)
                        #pragma unroll
                        for (int q = 0; q < 4; q++) sc[u][q] = sn[u][q];
                }
            }
            __syncthreads();
        }

        l0 += __shfl_xor_sync(0xffffffffu, l0, 1);
        l0 += __shfl_xor_sync(0xffffffffu, l0, 2);
        l1 += __shfl_xor_sync(0xffffffffu, l1, 1);
        l1 += __shfl_xor_sync(0xffffffffu, l1, 2);
    };

    // PASS 1: Hopfield update (V = K, aliased — K tiles only)
    flash_pass(Kin, 0);

    // Q2 = (O / l) * QSF; store fp16 to P region, reload as A-frags.
    {
        float s0 = QSF / l0, s1 = QSF / l1;
        #pragma unroll
        for (int j = 0; j < 8; j++) {
            *(__half2*)(Pwp +  g      * APH + j*8 + 2*t) =
                __floats2half2_rn(o[j][0] * s0, o[j][1] * s0);
            *(__half2*)(Pwp + (g + 8) * APH + j*8 + 2*t) =
                __floats2half2_rn(o[j][2] * s1, o[j][3] * s1);
        }
        __syncwarp();
        #pragma unroll
        for (int s = 0; s < 4; s++)
            ldsm4(qa[s][0], qa[s][1], qa[s][2], qa[s][3], pfA + s*32);
    }
    __syncthreads();

    // PASS 2: retrieval (real V)
    flash_pass(Vin, 1);

    // epilogue: O / l -> fp16 (consumed by gemm_out)
    float inv0 = 1.f / l0, inv1 = 1.f / l1;
    int r0 = q0 + w * 16 + g;
    __half* Op = Out + base;
    #pragma unroll
    for (int j = 0; j < 8; j++) {
        *(__half2*)&Op[(size_t)r0     * HDIM + j*8 + 2*t] =
            __floats2half2_rn(o[j][0] * inv0, o[j][1] * inv0);
        *(__half2*)&Op[(size_t)(r0+8) * HDIM + j*8 + 2*t] =
            __floats2half2_rn(o[j][2] * inv1, o[j][3] * inv1);
    }
}

// ---------------------------------------------------------------------------
// Launch
// ---------------------------------------------------------------------------
extern "C" void kernel_launch(void* const* d_in, const int* in_sizes, int n_in,
                              void* d_out, int out_size)
{
    const float* data = (const float*)d_in[0];
    const float* gk   = (const float*)d_in[1];
    const float* bk   = (const float*)d_in[2];
    const float* gq   = (const float*)d_in[3];
    const float* bq   = (const float*)d_in[4];
    const float* gv   = (const float*)d_in[5];
    const float* bv   = (const float*)d_in[6];
    const float* Wq   = (const float*)d_in[7];
    const float* bq2  = (const float*)d_in[8];
    const float* Wk   = (const float*)d_in[9];
    const float* bk2  = (const float*)d_in[10];
    const float* Wv   = (const float*)d_in[11];
    const float* bv2  = (const float*)d_in[12];
    const float* Wo   = (const float*)d_in[13];
    const float* bo   = (const float*)d_in[14];
    float* out = (float*)d_out;

    __half *xq, *xk, *xv, *Q, *K, *V, *O, *rWq, *rWk, *rWv, *rWo;
    cudaGetSymbolAddress((void**)&xq, g_xq);
    cudaGetSymbolAddress((void**)&xk, g_xk);
    cudaGetSymbolAddress((void**)&xv, g_xv);
    cudaGetSymbolAddress((void**)&Q,  g_Q);
    cudaGetSymbolAddress((void**)&K,  g_K);
    cudaGetSymbolAddress((void**)&V,  g_V);
    cudaGetSymbolAddress((void**)&O,  g_O);
    cudaGetSymbolAddress((void**)&rWq, g_Wq);
    cudaGetSymbolAddress((void**)&rWk, g_Wk);
    cudaGetSymbolAddress((void**)&rWv, g_Wv);
    cudaGetSymbolAddress((void**)&rWo, g_Wo);

    static int attr_done = 0;
    if (!attr_done) {
        cudaFuncSetAttribute(attn_fused, cudaFuncAttributeMaxDynamicSharedMemorySize, ATTN_SMEM);
        attr_done = 1;
    }

    dim3 rwgrid(DD / 32, DD / 32, 4);
    dim3 rwblk(32, 8);
    roundw_t<<<rwgrid, rwblk>>>(Wq, Wk, Wv, Wo, rWq, rWk, rWv, rWo);

    ln3_kernel<<<TOK, 256>>>(data, gk, bk, gq, bq, gv, bv, xq, xk, xv);

    dim3 qkvgrid(DD / 128, TOK / 128, 3);       // (8, 32, 3)
    gemm_qkv<<<qkvgrid, 256>>>(xq, xk, xv, rWq, rWk, rWv, bq2, bk2, bv2, Q, K, V);

    dim3 agrid(SS / 128, BB * HH);              // (16, 32)
    attn_fused<<<agrid, 256, ATTN_SMEM>>>(Q, K, V, O);

    dim3 ogrid(DD / 128, TOK / 128);
    gemm_out<<<ogrid, 256>>>(O, rWo, bo, out);
}

// round 16
// speedup vs baseline: 2.4675x; 1.0454x over previous
#include <cuda_runtime.h>
#include <cuda_fp16.h>
#include <math.h>

// Problem constants
#define BB   2
#define SS   2048
#define DD   1024
#define HH   16
#define HDIM 64
#define TOK  (BB*SS)           // 4096 rows
#define NSCALE 0.125f          // 1/sqrt(64)
#define LOG2E  1.4426950408889634f
#define QSF   (NSCALE * LOG2E)

// ---------------------------------------------------------------------------
// Scratch (static __device__ arrays; no allocation allowed)
// ---------------------------------------------------------------------------
__device__ __half g_xq[TOK*DD];
__device__ __half g_xk[TOK*DD];
__device__ __half g_xv[TOK*DD];
__device__ __half g_Q [TOK*DD];   // head layout [B,H,S,HD], PRE-SCALED by QSF
__device__ __half g_K [TOK*DD];   // head layout
__device__ __half g_V [TOK*DD];
__device__ __half g_O [TOK*DD];   // attention output, head layout
__device__ __half g_Wq[DD*DD];    // fp16, TRANSPOSED [n][k]
__device__ __half g_Wk[DD*DD];
__device__ __half g_Wv[DD*DD];
__device__ __half g_Wo[DD*DD];

// ---------------------------------------------------------------------------
// helpers
// ---------------------------------------------------------------------------
__device__ __forceinline__ float ex2(float x) {
    float y;
    asm("ex2.approx.ftz.f32 %0, %1;" : "=f"(y) : "f"(x));
    return y;
}
__device__ __forceinline__ void mma16(float* d, const unsigned* a, unsigned b0, unsigned b1) {
    asm volatile(
        "mma.sync.aligned.m16n8k16.row.col.f32.f16.f16.f32 "
        "{%0,%1,%2,%3}, {%4,%5,%6,%7}, {%8,%9}, {%0,%1,%2,%3};"
        : "+f"(d[0]), "+f"(d[1]), "+f"(d[2]), "+f"(d[3])
        : "r"(a[0]), "r"(a[1]), "r"(a[2]), "r"(a[3]), "r"(b0), "r"(b1));
}
__device__ __forceinline__ void ldsm4(unsigned& r0, unsigned& r1, unsigned& r2, unsigned& r3,
                                      unsigned addr) {
    asm volatile("ldmatrix.sync.aligned.m8n8.x4.shared.b16 {%0,%1,%2,%3}, [%4];"
        : "=r"(r0), "=r"(r1), "=r"(r2), "=r"(r3) : "r"(addr));
}
__device__ __forceinline__ void ldsm4t(unsigned& r0, unsigned& r1, unsigned& r2, unsigned& r3,
                                       unsigned addr) {
    asm volatile("ldmatrix.sync.aligned.m8n8.x4.trans.shared.b16 {%0,%1,%2,%3}, [%4];"
        : "=r"(r0), "=r"(r1), "=r"(r2), "=r"(r3) : "r"(addr));
}
__device__ __forceinline__ unsigned h2pack(float a, float b) {
    __half2 h = __floats2half2_rn(a, b);
    return *(unsigned*)&h;
}
__device__ __forceinline__ void cpa16(unsigned dst, const void* src) {
    asm volatile("cp.async.cg.shared.global [%0], [%1], 16;" :: "r"(dst), "l"(src));
}
__device__ __forceinline__ void cpa_commit() { asm volatile("cp.async.commit_group;"); }
__device__ __forceinline__ void cpa_wait0()  { asm volatile("cp.async.wait_group 0;"); }
__device__ __forceinline__ void cpa_wait1()  { asm volatile("cp.async.wait_group 1;"); }

// ---------------------------------------------------------------------------
// Weight convert + transpose: dst[n][k] = fp16(src[k][n])
// grid (DD/32, DD/32, 4), block (32, 8)
// ---------------------------------------------------------------------------
__global__ __launch_bounds__(256) void roundw_t(
    const float* __restrict__ w0, const float* __restrict__ w1,
    const float* __restrict__ w2, const float* __restrict__ w3,
    __half* __restrict__ d0, __half* __restrict__ d1,
    __half* __restrict__ d2, __half* __restrict__ d3)
{
    __shared__ float tile[32][33];
    const float* src; __half* dst;
    switch (blockIdx.z) {
        case 0: src = w0; dst = d0; break;
        case 1: src = w1; dst = d1; break;
        case 2: src = w2; dst = d2; break;
        default: src = w3; dst = d3; break;
    }
    int k0 = blockIdx.x * 32, n0 = blockIdx.y * 32;
    int x = threadIdx.x;
    #pragma unroll
    for (int r = threadIdx.y; r < 32; r += 8)
        tile[r][x] = src[(size_t)(k0 + r) * DD + n0 + x];
    __syncthreads();
    #pragma unroll
    for (int r = threadIdx.y; r < 32; r += 8)
        dst[(size_t)(n0 + r) * DD + k0 + x] = __float2half_rn(tile[x][r]);
}

// ---------------------------------------------------------------------------
// Block reduction (256 threads)
// ---------------------------------------------------------------------------
__device__ __forceinline__ float blk_sum256(float v) {
    __shared__ float red[8];
    int lane = threadIdx.x & 31;
    int w    = threadIdx.x >> 5;
    #pragma unroll
    for (int o = 16; o > 0; o >>= 1) v += __shfl_xor_sync(0xffffffffu, v, o);
    __syncthreads();
    if (lane == 0) red[w] = v;
    __syncthreads();
    return red[0]+red[1]+red[2]+red[3]+red[4]+red[5]+red[6]+red[7];
}

// ---------------------------------------------------------------------------
// Fused triple LayerNorm (fp16 outputs)
// ---------------------------------------------------------------------------
__global__ __launch_bounds__(256) void ln3_kernel(
    const float* __restrict__ data,
    const float* __restrict__ gk, const float* __restrict__ bk,
    const float* __restrict__ gq, const float* __restrict__ bq,
    const float* __restrict__ gv, const float* __restrict__ bv,
    __half* __restrict__ xq, __half* __restrict__ xk, __half* __restrict__ xv)
{
    int row = blockIdx.x;
    int t   = threadIdx.x;
    const float4 x4 = ((const float4*)(data + (size_t)row * DD))[t];
    float s = x4.x + x4.y + x4.z + x4.w;
    float mean = blk_sum256(s) * (1.0f / DD);
    float d0 = x4.x - mean, d1 = x4.y - mean, d2 = x4.z - mean, d3 = x4.w - mean;
    float sq = d0*d0 + d1*d1 + d2*d2 + d3*d3;
    float var = blk_sum256(sq) * (1.0f / DD);
    float r = rsqrtf(var + 1e-5f);
    float n0 = d0*r, n1 = d1*r, n2 = d2*r, n3 = d3*r;

    float4 g4, b4;
    size_t base = (size_t)row * DD + t * 4;

    g4 = ((const float4*)gq)[t]; b4 = ((const float4*)bq)[t];
    *(__half2*)&xq[base]     = __floats2half2_rn(n0*g4.x + b4.x, n1*g4.y + b4.y);
    *(__half2*)&xq[base + 2] = __floats2half2_rn(n2*g4.z + b4.z, n3*g4.w + b4.w);

    g4 = ((const float4*)gk)[t]; b4 = ((const float4*)bk)[t];
    *(__half2*)&xk[base]     = __floats2half2_rn(n0*g4.x + b4.x, n1*g4.y + b4.y);
    *(__half2*)&xk[base + 2] = __floats2half2_rn(n2*g4.z + b4.z, n3*g4.w + b4.w);

    g4 = ((const float4*)gv)[t]; b4 = ((const float4*)bv)[t];
    *(__half2*)&xv[base]     = __floats2half2_rn(n0*g4.x + b4.x, n1*g4.y + b4.y);
    *(__half2*)&xv[base + 2] = __floats2half2_rn(n2*g4.z + b4.z, n3*g4.w + b4.w);
}

// ---------------------------------------------------------------------------
// fp16 GEMM body (mma.m16n8k16 + ldmatrix b16), cp.async 2-stage, BK=64.
// A [M,K] fp16 (or head-layout gather), W TRANSPOSED [N,K] fp16.
// OUT: 0 = fp32 row-major (Cf) | 1 = fp16 head layout (Ch), scaled by qscale
// ---------------------------------------------------------------------------
template<int MODE_IN, int OUT>
__device__ __forceinline__ void gemm_body(
    const __half* __restrict__ A, const __half* __restrict__ Wt,
    const float* __restrict__ bias, float* __restrict__ Cf,
    __half* __restrict__ Ch, float qscale)
{
    constexpr int BM = 128, BK = 64;
    constexpr int PH = 72;              // row pitch in halves (144B, conflict-free)
    constexpr int TSZ = BM * PH;        // halves per stage
    __shared__ __half As[2 * TSZ];
    __shared__ __half Bs[2 * TSZ];

    int tid  = threadIdx.x;
    int lane = tid & 31;
    int w    = tid >> 5;
    int g    = lane >> 2;
    int t    = lane & 3;
    int wm   = (w >> 2) * 64;
    int wn   = (w & 3) * 32;
    int bm   = blockIdx.y * BM;
    int bn   = blockIdx.x * BM;

    int lr = tid >> 1;                  // 0..127
    int lc = (tid & 1) * 32;            // halves: 0 or 32

    unsigned as_base = (unsigned)__cvta_generic_to_shared(As);
    unsigned bs_base = (unsigned)__cvta_generic_to_shared(Bs);

    // fragment base addresses (bytes)
    unsigned a_ld = as_base + (((lane & 15) * PH + (lane >> 4) * 8) * 2);
    unsigned b_ld = bs_base + (((lane & 7)  * PH + (lane >> 3) * 8) * 2);

    float acc[4][4][4];
    #pragma unroll
    for (int i = 0; i < 4; i++)
        #pragma unroll
        for (int j = 0; j < 4; j++)
            #pragma unroll
            for (int q = 0; q < 4; q++) acc[i][j][q] = 0.f;

    auto load_tile = [&](int it, int stg) {
        int kk = it * BK;
        int gm = bm + lr;
        int gk = kk + lc;
        const __half* pa;
        if (MODE_IN == 0) {
            pa = &A[(size_t)gm * DD + gk];
        } else {
            int b  = gm >> 11, s2 = gm & (SS - 1);
            int h  = gk >> 6,  hd = gk & (HDIM - 1);
            pa = &A[(((size_t)(b*HH + h) * SS + s2) * HDIM) + hd];
        }
        unsigned da = as_base + (stg * TSZ + lr * PH + lc) * 2;
        #pragma unroll
        for (int i = 0; i < 4; i++) cpa16(da + i*16, pa + i*8);
        const __half* pb = &Wt[(size_t)(bn + lr) * DD + kk + lc];
        unsigned db = bs_base + (stg * TSZ + lr * PH + lc) * 2;
        #pragma unroll
        for (int i = 0; i < 4; i++) cpa16(db + i*16, pb + i*8);
    };

    constexpr int KITER = DD / BK;      // 16
    load_tile(0, 0);
    cpa_commit();

    for (int it = 0; it < KITER; it++) {
        int cur = it & 1;
        if (it + 1 < KITER) {
            load_tile(it + 1, cur ^ 1);
            cpa_commit();
            cpa_wait1();
        } else {
            cpa_wait0();
        }
        __syncthreads();

        unsigned ab = a_ld + cur * TSZ * 2;
        unsigned bb = b_ld + cur * TSZ * 2;

        #pragma unroll
        for (int kh = 0; kh < 2; kh++) {         // 32-half chunks -> 2 ksteps each
            unsigned bf[4][4];
            #pragma unroll
            for (int ni = 0; ni < 4; ni++)
                ldsm4(bf[ni][0], bf[ni][1], bf[ni][2], bf[ni][3],
                      bb + ((wn + ni*8) * PH + kh*32) * 2);
            #pragma unroll
            for (int kp = 0; kp < 2; kp++) {
                unsigned af[4][4];
                #pragma unroll
                for (int mi = 0; mi < 4; mi++)
                    ldsm4(af[mi][0], af[mi][1], af[mi][2], af[mi][3],
                          ab + ((wm + mi*16) * PH + kh*32 + kp*16) * 2);
                #pragma unroll
                for (int mi = 0; mi < 4; mi++)
                    #pragma unroll
                    for (int ni = 0; ni < 4; ni++)
                        mma16(acc[mi][ni], af[mi], bf[ni][2*kp], bf[ni][2*kp + 1]);
            }
        }
        __syncthreads();
    }

    #pragma unroll
    for (int mi = 0; mi < 4; mi++) {
        #pragma unroll
        for (int ni = 0; ni < 4; ni++) {
            int row = bm + wm + mi * 16 + g;
            int col = bn + wn + ni * 8 + 2 * t;
            float2 bia = *(const float2*)&bias[col];
            float v00 = acc[mi][ni][0] + bia.x, v01 = acc[mi][ni][1] + bia.y;
            float v10 = acc[mi][ni][2] + bia.x, v11 = acc[mi][ni][3] + bia.y;
            if (OUT == 0) {
                *(float2*)&Cf[(size_t)row * DD + col]       = make_float2(v00, v01);
                *(float2*)&Cf[(size_t)(row + 8) * DD + col] = make_float2(v10, v11);
            } else {
                v00 *= qscale; v01 *= qscale; v10 *= qscale; v11 *= qscale;
                int h = col >> 6, hd = col & (HDIM - 1);
                int b0i = row >> 11,       s0 = row & (SS - 1);
                int b1i = (row + 8) >> 11, s1 = (row + 8) & (SS - 1);
                *(__half2*)&Ch[((size_t)(b0i*HH + h) * SS + s0) * HDIM + hd] =
                    __floats2half2_rn(v00, v01);
                *(__half2*)&Ch[((size_t)(b1i*HH + h) * SS + s1) * HDIM + hd] =
                    __floats2half2_rn(v10, v11);
            }
        }
    }
}

// Batched Q/K/V projection: grid (8, 32, 3). Q output pre-scaled by QSF.
__global__ __launch_bounds__(256, 2) void gemm_qkv(
    const __half* __restrict__ xq, const __half* __restrict__ xk, const __half* __restrict__ xv,
    const __half* __restrict__ Wq, const __half* __restrict__ Wk, const __half* __restrict__ Wv,
    const float* __restrict__ bq, const float* __restrict__ bk, const float* __restrict__ bv,
    __half* __restrict__ Q, __half* __restrict__ K, __half* __restrict__ V)
{
    if (blockIdx.z == 0)      gemm_body<0, 1>(xq, Wq, bq, nullptr, Q, QSF);
    else if (blockIdx.z == 1) gemm_body<0, 1>(xk, Wk, bk, nullptr, K, 1.0f);
    else                      gemm_body<0, 1>(xv, Wv, bv, nullptr, V, 1.0f);
}

// Output projection: grid (8, 32), fp32 out
__global__ __launch_bounds__(256, 2) void gemm_out(
    const __half* __restrict__ A, const __half* __restrict__ Wt,
    const float* __restrict__ bias, float* __restrict__ C)
{
    gemm_body<1, 0>(A, Wt, bias, C, nullptr, 1.0f);
}

// ---------------------------------------------------------------------------
// FUSED double-pass flash attention, fp16 m16n8k16.
// P and Q2 stay IN REGISTERS (C-fragment layout of S == A-fragment layout
// of P for m16n8k16) — no P smem region, no STS/LDSM round trip.
//   pass 1: Q2 = softmax(b Q K^T) K      (V tile := K tile, no extra load)
//   pass 2: O  = softmax(b Q2 K^T) V
// Q is PRE-SCALED by QSF (beta*log2e); softmax = 2^s / sum.
// 256 threads = 8 warps; CTA = 128 queries (16/warp); K-tile 64 keys.
// Smem (halves): K[2][64*72] | V[2][64*72]  (~37 KB)
// ---------------------------------------------------------------------------
#define APH 72
#define KTILE (64*APH)
#define ATTN_SMEM (4*KTILE*2)

__global__ __launch_bounds__(256, 2) void attn_fused(
    const __half* __restrict__ Qin, const __half* __restrict__ Kin,
    const __half* __restrict__ Vin, __half* __restrict__ Out)
{
    extern __shared__ __half smh[];
    __half* Ks = smh;                   // [2][KTILE]  key x hd
    __half* Vs = smh + 2 * KTILE;       // [2][KTILE]  key x hd (natural layout)
    unsigned ks_base = (unsigned)__cvta_generic_to_shared(Ks);
    unsigned vs_base = (unsigned)__cvta_generic_to_shared(Vs);

    int tid  = threadIdx.x;
    int lane = tid & 31;
    int w    = tid >> 5;
    int g    = lane >> 2;
    int t    = lane & 3;
    int bh   = blockIdx.y;
    int q0   = blockIdx.x * 128;
    size_t base = (size_t)bh * SS * HDIM;

    int lrow = tid >> 2;                // 0..63
    int lch  = (tid & 3) * 16;          // halves: 0,16,32,48

    // fragment per-lane offsets (bytes)
    unsigned kfB   = ks_base + (((lane & 7) * APH + (lane >> 3) * 8) * 2);         // K: B x4
    unsigned vlane = (((lane & 15) * APH + (lane >> 4) * 8) * 2);                   // V: B x4 trans

    // Q fragments (already x QSF in global)
    unsigned qa[4][4];
    {
        const __half* Qp = Qin + base;
        int r0 = q0 + w * 16 + g;
        #pragma unroll
        for (int s = 0; s < 4; s++) {
            qa[s][0] = *(const unsigned*)&Qp[(size_t)r0     * HDIM + s*16 + 2*t    ];
            qa[s][1] = *(const unsigned*)&Qp[(size_t)(r0+8) * HDIM + s*16 + 2*t    ];
            qa[s][2] = *(const unsigned*)&Qp[(size_t)r0     * HDIM + s*16 + 2*t + 8];
            qa[s][3] = *(const unsigned*)&Qp[(size_t)(r0+8) * HDIM + s*16 + 2*t + 8];
        }
    }

    float o[8][4];
    float l0, l1;
    constexpr int NT = SS / 64;         // 32

    // PASS = 0: V tile aliases K tile (no V loads). PASS = 1: load V too.
    auto flash_pass = [&](const __half* __restrict__ Vsrc, int loadV) {
        #pragma unroll
        for (int j = 0; j < 8; j++)
            #pragma unroll
            for (int q = 0; q < 4; q++) o[j][q] = 0.f;
        l0 = 0.f; l1 = 0.f;

        unsigned vbase = loadV ? vs_base : ks_base;

        auto load_kv = [&](int kt, int stg) {
            const __half* Kp = Kin + base + (size_t)(kt*64 + lrow) * HDIM + lch;
            unsigned kd = ks_base + (stg * KTILE + lrow * APH + lch) * 2;
            cpa16(kd,      Kp);
            cpa16(kd + 16, Kp + 8);
            if (loadV) {
                const __half* Vp = Vsrc + base + (size_t)(kt*64 + lrow) * HDIM + lch;
                unsigned vd = vs_base + (stg * KTILE + lrow * APH + lch) * 2;
                cpa16(vd,      Vp);
                cpa16(vd + 16, Vp + 8);
            }
        };

        load_kv(0, 0);
        cpa_commit();

        for (int kt = 0; kt < NT; kt++) {
            int cur = kt & 1;
            if (kt + 1 < NT) {
                load_kv(kt + 1, cur ^ 1);
                cpa_commit();
                cpa_wait1();
            } else {
                cpa_wait0();
            }
            __syncthreads();

            unsigned kf = kfB + cur * KTILE * 2;
            unsigned vf = vbase + cur * KTILE * 2 + vlane;

            // S for one 8-key n-block (hd = 64 -> 4 ksteps)
            auto compute_S = [&](int n, float* d) {
                d[0] = 0.f; d[1] = 0.f; d[2] = 0.f; d[3] = 0.f;
                unsigned b0, b1, b2, b3;
                ldsm4(b0, b1, b2, b3, kf + (n*8*APH) * 2);
                mma16(d, qa[0], b0, b1);
                mma16(d, qa[1], b2, b3);
                ldsm4(b0, b1, b2, b3, kf + (n*8*APH + 32) * 2);
                mma16(d, qa[2], b0, b1);
                mma16(d, qa[3], b2, b3);
            };

            float sc[2][4], sn[2][4];
            compute_S(0, sc[0]);
            compute_S(1, sc[1]);

            #pragma unroll
            for (int i = 0; i < 4; i++) {
                // softmax of group i (16 keys); P built directly as A-frags
                float p00 = ex2(sc[0][0]), p01 = ex2(sc[0][1]);
                float p02 = ex2(sc[0][2]), p03 = ex2(sc[0][3]);
                float p10 = ex2(sc[1][0]), p11 = ex2(sc[1][1]);
                float p12 = ex2(sc[1][2]), p13 = ex2(sc[1][3]);
                l0 += (p00 + p01) + (p10 + p11);
                l1 += (p02 + p03) + (p12 + p13);
                unsigned pa[4];
                pa[0] = h2pack(p00, p01);   // row g,   keys 2t..2t+1 of block 2i
                pa[1] = h2pack(p02, p03);   // row g+8, block 2i
                pa[2] = h2pack(p10, p11);   // row g,   block 2i+1
                pa[3] = h2pack(p12, p13);   // row g+8, block 2i+1
                // S of group i+1 in the MUFU shadow
                if (i < 3) {
                    compute_S(2*i + 2, sn[0]);
                    compute_S(2*i + 3, sn[1]);
                }
                // O += P V for group i: B-frags via ldmatrix.x4.trans from the
                // natural-layout V tile (rows = keys 16i.., col pair j, j+1)
                #pragma unroll
                for (int j = 0; j < 8; j += 2) {
                    unsigned v0, v1, v2, v3;
                    ldsm4t(v0, v1, v2, v3, vf + (i*16*APH + j*8) * 2);
                    mma16(o[j],     pa, v0, v1);
                    mma16(o[j + 1], pa, v2, v3);
                }
                if (i < 3) {
                    #pragma unroll
                    for (int u = 0; u < 2; u++)
                        #pragma unroll
                        for (int q = 0; q < 4; q++) sc[u][q] = sn[u][q];
                }
            }
            __syncthreads();
        }

        l0 += __shfl_xor_sync(0xffffffffu, l0, 1);
        l0 += __shfl_xor_sync(0xffffffffu, l0, 2);
        l1 += __shfl_xor_sync(0xffffffffu, l1, 1);
        l1 += __shfl_xor_sync(0xffffffffu, l1, 2);
    };

    // PASS 1: Hopfield update (V = K, aliased — K tiles only)
    flash_pass(Kin, 0);

    // Q2 = (O / l) * QSF — pure register conversion into A-frag layout.
    // For kstep s (hd s*16..s*16+15): a0 = (row g, hd s*16+2t..+1) = o[2s] c0,c1;
    // a1 = (g+8) = o[2s] c2,c3; a2/a3 from o[2s+1].
    {
        float s0 = QSF / l0, s1 = QSF / l1;
        #pragma unroll
        for (int s = 0; s < 4; s++) {
            qa[s][0] = h2pack(o[2*s    ][0] * s0, o[2*s    ][1] * s0);
            qa[s][1] = h2pack(o[2*s    ][2] * s1, o[2*s    ][3] * s1);
            qa[s][2] = h2pack(o[2*s + 1][0] * s0, o[2*s + 1][1] * s0);
            qa[s][3] = h2pack(o[2*s + 1][2] * s1, o[2*s + 1][3] * s1);
        }
    }
    __syncthreads();

    // PASS 2: retrieval (real V)
    flash_pass(Vin, 1);

    // epilogue: O / l -> fp16 (consumed by gemm_out)
    float inv0 = 1.f / l0, inv1 = 1.f / l1;
    int r0 = q0 + w * 16 + g;
    __half* Op = Out + base;
    #pragma unroll
    for (int j = 0; j < 8; j++) {
        *(__half2*)&Op[(size_t)r0     * HDIM + j*8 + 2*t] =
            __floats2half2_rn(o[j][0] * inv0, o[j][1] * inv0);
        *(__half2*)&Op[(size_t)(r0+8) * HDIM + j*8 + 2*t] =
            __floats2half2_rn(o[j][2] * inv1, o[j][3] * inv1);
    }
}

// ---------------------------------------------------------------------------
// Launch
// ---------------------------------------------------------------------------
extern "C" void kernel_launch(void* const* d_in, const int* in_sizes, int n_in,
                              void* d_out, int out_size)
{
    const float* data = (const float*)d_in[0];
    const float* gk   = (const float*)d_in[1];
    const float* bk   = (const float*)d_in[2];
    const float* gq   = (const float*)d_in[3];
    const float* bq   = (const float*)d_in[4];
    const float* gv   = (const float*)d_in[5];
    const float* bv   = (const float*)d_in[6];
    const float* Wq   = (const float*)d_in[7];
    const float* bq2  = (const float*)d_in[8];
    const float* Wk   = (const float*)d_in[9];
    const float* bk2  = (const float*)d_in[10];
    const float* Wv   = (const float*)d_in[11];
    const float* bv2  = (const float*)d_in[12];
    const float* Wo   = (const float*)d_in[13];
    const float* bo   = (const float*)d_in[14];
    float* out = (float*)d_out;

    __half *xq, *xk, *xv, *Q, *K, *V, *O, *rWq, *rWk, *rWv, *rWo;
    cudaGetSymbolAddress((void**)&xq, g_xq);
    cudaGetSymbolAddress((void**)&xk, g_xk);
    cudaGetSymbolAddress((void**)&xv, g_xv);
    cudaGetSymbolAddress((void**)&Q,  g_Q);
    cudaGetSymbolAddress((void**)&K,  g_K);
    cudaGetSymbolAddress((void**)&V,  g_V);
    cudaGetSymbolAddress((void**)&O,  g_O);
    cudaGetSymbolAddress((void**)&rWq, g_Wq);
    cudaGetSymbolAddress((void**)&rWk, g_Wk);
    cudaGetSymbolAddress((void**)&rWv, g_Wv);
    cudaGetSymbolAddress((void**)&rWo, g_Wo);

    static int attr_done = 0;
    if (!attr_done) {
        cudaFuncSetAttribute(attn_fused, cudaFuncAttributeMaxDynamicSharedMemorySize, ATTN_SMEM);
        attr_done = 1;
    }

    dim3 rwgrid(DD / 32, DD / 32, 4);
    dim3 rwblk(32, 8);
    roundw_t<<<rwgrid, rwblk>>>(Wq, Wk, Wv, Wo, rWq, rWk, rWv, rWo);

    ln3_kernel<<<TOK, 256>>>(data, gk, bk, gq, bq, gv, bv, xq, xk, xv);

    dim3 qkvgrid(DD / 128, TOK / 128, 3);       // (8, 32, 3)
    gemm_qkv<<<qkvgrid, 256>>>(xq, xk, xv, rWq, rWk, rWv, bq2, bk2, bv2, Q, K, V);

    dim3 agrid(SS / 128, BB * HH);              // (16, 32)
    attn_fused<<<agrid, 256, ATTN_SMEM>>>(Q, K, V, O);

    dim3 ogrid(DD / 128, TOK / 128);
    gemm_out<<<ogrid, 256>>>(O, rWo, bo, out);
}